// round 1
// baseline (speedup 1.0000x reference)
#include <cuda_runtime.h>
#include <math.h>
#include <stdint.h>

// ---------------- problem constants ----------------
#define NLAYERS 4
#define NHEADS  8
#define DMODEL  256
#define DFF     1024
#define BATCH   2
#define SEQ     2048
#define MTOT    (BATCH * SEQ)   // 4096 rows
#define HD      32              // head dim

// ---------------- scratch (device globals; no allocation allowed) ----------
__device__ float g_h   [MTOT * DMODEL];
__device__ float g_ln  [MTOT * DMODEL];
__device__ float g_q   [MTOT * DMODEL];
__device__ float g_k   [MTOT * DMODEL];
__device__ float g_v   [MTOT * DMODEL];
__device__ float g_attn[MTOT * DMODEL];
__device__ float g_ff  [MTOT * DFF];
__device__ float g_unc [BATCH * NHEADS * SEQ];

// ---------------- layernorm: one block (256 threads) per row ---------------
__global__ void ln_kernel(const float* __restrict__ x,
                          const float* __restrict__ gamma,
                          const float* __restrict__ beta,
                          float* __restrict__ y)
{
    int row = blockIdx.x;
    int tid = threadIdx.x;            // 256 threads == DMODEL
    float v = x[(size_t)row * DMODEL + tid];

    __shared__ float red[8];
    // mean
    float s = v;
    #pragma unroll
    for (int o = 16; o > 0; o >>= 1) s += __shfl_xor_sync(0xffffffffu, s, o);
    if ((tid & 31) == 0) red[tid >> 5] = s;
    __syncthreads();
    float mean = 0.f;
    #pragma unroll
    for (int i = 0; i < 8; i++) mean += red[i];
    mean *= (1.0f / DMODEL);
    __syncthreads();
    // var
    float d = v - mean;
    float s2 = d * d;
    #pragma unroll
    for (int o = 16; o > 0; o >>= 1) s2 += __shfl_xor_sync(0xffffffffu, s2, o);
    if ((tid & 31) == 0) red[tid >> 5] = s2;
    __syncthreads();
    float var = 0.f;
    #pragma unroll
    for (int i = 0; i < 8; i++) var += red[i];
    var *= (1.0f / DMODEL);

    y[(size_t)row * DMODEL + tid] = d * rsqrtf(var + 1e-5f) * gamma[tid] + beta[tid];
}

// ---------------- generic fp32 GEMM: C = epi(A[M,K] @ B[K,N] + bias) -------
// EPI: 0 = bias only, 1 = bias + residual, 2 = bias + exact GELU
// tiles: BM=BN=64, BK=16, 256 threads, 4x4 per thread. All dims divide evenly.
template <int EPI>
__global__ void gemm_kernel(const float* __restrict__ A,
                            const float* __restrict__ Bm,
                            const float* __restrict__ bias,
                            const float* __restrict__ res,
                            float* __restrict__ C,
                            int N, int K)
{
    __shared__ __align__(16) float As[16][64];
    __shared__ __align__(16) float Bs[16][64];

    int tid = threadIdx.x;
    int tx = tid & 15, ty = tid >> 4;
    int m0 = blockIdx.y * 64;
    int n0 = blockIdx.x * 64;

    float c[4][4] = {};

    for (int k0 = 0; k0 < K; k0 += 16) {
        #pragma unroll
        for (int e = 0; e < 4; e++) {
            int idx = tid + e * 256;
            int m = idx >> 4, kk = idx & 15;
            As[kk][m] = A[(size_t)(m0 + m) * K + k0 + kk];
        }
        #pragma unroll
        for (int e = 0; e < 4; e++) {
            int idx = tid + e * 256;
            int kk = idx >> 6, n = idx & 63;
            Bs[kk][n] = Bm[(size_t)(k0 + kk) * N + n0 + n];
        }
        __syncthreads();
        #pragma unroll
        for (int kk = 0; kk < 16; kk++) {
            float4 a4 = *(const float4*)&As[kk][ty * 4];
            float4 b4 = *(const float4*)&Bs[kk][tx * 4];
            float av[4] = {a4.x, a4.y, a4.z, a4.w};
            float bv[4] = {b4.x, b4.y, b4.z, b4.w};
            #pragma unroll
            for (int i = 0; i < 4; i++)
                #pragma unroll
                for (int j = 0; j < 4; j++)
                    c[i][j] = fmaf(av[i], bv[j], c[i][j]);
        }
        __syncthreads();
    }

    #pragma unroll
    for (int i = 0; i < 4; i++) {
        int row = m0 + ty * 4 + i;
        #pragma unroll
        for (int j = 0; j < 4; j++) {
            int col = n0 + tx * 4 + j;
            float v = c[i][j] + bias[col];
            if (EPI == 1) v += res[(size_t)row * N + col];
            if (EPI == 2) v = 0.5f * v * (1.0f + erff(v * 0.70710678118654752f));
            C[(size_t)row * N + col] = v;
        }
    }
}

// ---------------- fused evidential attention ------------------------------
// One block = 64 queries of one (b,h). Streams K/V in 64-key tiles.
// evidence e = scale*exp(s/sqrt(hd)) + (1+bias); single pass: no max, no Vsum.
// Writes attn (head-concat layout [B,L,D]) and accumulates unc += L/denom.
__global__ void attn_kernel(const float* __restrict__ Q,
                            const float* __restrict__ Kx,
                            const float* __restrict__ V,
                            float* __restrict__ out,
                            float* __restrict__ unc,
                            const float* __restrict__ ev_scale,
                            const float* __restrict__ ev_bias,
                            int layer)
{
    // transposed Q/K tiles: [dim][key] for conflict-free float4 in score phase
    __shared__ __align__(16) float Qst[32][68];
    __shared__ __align__(16) float Kst[32][68];
    __shared__ __align__(16) float Vs [64][36];
    __shared__ float Es[64][65];

    int tid = threadIdx.x;                 // 256
    int bh = blockIdx.y;                   // b*8 + h
    int b  = bh >> 3, h = bh & 7;
    int q0 = blockIdx.x * 64;

    float scale = ev_scale[layer];
    float opb   = 1.0f + ev_bias[layer];
    const float inv_sqrt_hd = 0.17677669529663687f;   // 1/sqrt(32)

    const float* Qb = Q  + (size_t)b * SEQ * DMODEL + h * HD;
    const float* Kb = Kx + (size_t)b * SEQ * DMODEL + h * HD;
    const float* Vb = V  + (size_t)b * SEQ * DMODEL + h * HD;

    // load Q tile (transposed into smem)
    #pragma unroll
    for (int e = 0; e < 8; e++) {
        int idx = tid + e * 256;
        int r = idx >> 5, c = idx & 31;
        Qst[c][r] = Qb[(size_t)(q0 + r) * DMODEL + c];
    }

    int ty = tid >> 4, tx = tid & 15;      // score phase: 4q x 4k per thread
    int qq = tid >> 2, dblk = tid & 3;     // EV phase: 1q x 8d per thread
    int d0 = dblk * 8;

    float EV[8] = {0, 0, 0, 0, 0, 0, 0, 0};
    float ESr = 0.f;

    for (int kb = 0; kb < SEQ; kb += 64) {
        __syncthreads();   // protect Kst/Vs/Es from previous iteration readers
        #pragma unroll
        for (int e = 0; e < 8; e++) {
            int idx = tid + e * 256;
            int r = idx >> 5, c = idx & 31;
            Kst[c][r] = Kb[(size_t)(kb + r) * DMODEL + c];
            Vs[r][c]  = Vb[(size_t)(kb + r) * DMODEL + c];
        }
        __syncthreads();

        // ---- scores: s[4q][4k] over hd=32 ----
        float s[4][4] = {};
        #pragma unroll
        for (int kk = 0; kk < HD; kk++) {
            float4 a4 = *(const float4*)&Qst[kk][ty * 4];
            float4 b4 = *(const float4*)&Kst[kk][tx * 4];
            float av[4] = {a4.x, a4.y, a4.z, a4.w};
            float bv[4] = {b4.x, b4.y, b4.z, b4.w};
            #pragma unroll
            for (int i = 0; i < 4; i++)
                #pragma unroll
                for (int j = 0; j < 4; j++)
                    s[i][j] = fmaf(av[i], bv[j], s[i][j]);
        }
        #pragma unroll
        for (int i = 0; i < 4; i++)
            #pragma unroll
            for (int j = 0; j < 4; j++)
                Es[ty * 4 + i][tx * 4 + j] =
                    fmaf(scale, __expf(s[i][j] * inv_sqrt_hd), opb);
        __syncthreads();

        // ---- EV accumulation: each thread 1 query x 8 dims ----
        #pragma unroll 4
        for (int k = 0; k < 64; k++) {
            float e = Es[qq][k];
            ESr += e;                       // same value across the 4 dblk peers
            float4 v0 = *(const float4*)&Vs[k][d0];
            float4 v1 = *(const float4*)&Vs[k][d0 + 4];
            EV[0] = fmaf(e, v0.x, EV[0]);
            EV[1] = fmaf(e, v0.y, EV[1]);
            EV[2] = fmaf(e, v0.z, EV[2]);
            EV[3] = fmaf(e, v0.w, EV[3]);
            EV[4] = fmaf(e, v1.x, EV[4]);
            EV[5] = fmaf(e, v1.y, EV[5]);
            EV[6] = fmaf(e, v1.z, EV[6]);
            EV[7] = fmaf(e, v1.w, EV[7]);
        }
    }

    float invd = 1.0f / ESr;
    float* orow = out + (size_t)b * SEQ * DMODEL + (size_t)(q0 + qq) * DMODEL + h * HD + d0;
    #pragma unroll
    for (int j = 0; j < 8; j++) orow[j] = EV[j] * invd;
    if (dblk == 0)
        unc[(size_t)bh * SEQ + q0 + qq] += (float)SEQ * invd;
}

// ---------------- small utility kernels ------------------------------------
__global__ void zero_unc_kernel()
{
    int i = blockIdx.x * blockDim.x + threadIdx.x;
    if (i < BATCH * NHEADS * SEQ) g_unc[i] = 0.f;
}

__global__ void finalize_kernel(float* __restrict__ out)
{
    int i = blockIdx.x * blockDim.x + threadIdx.x;
    if (i < BATCH * NHEADS * SEQ) {
        float a = g_unc[i] * 0.25f;                 // avg over 4 layers
        out[MTOT * DMODEL + i] = a;                 // avg_unc
        out[MTOT * DMODEL + BATCH * NHEADS * SEQ + i] = (a > 0.3f) ? 1.0f : 0.0f;
    }
}

// ---------------- launch ----------------------------------------------------
extern "C" void kernel_launch(void* const* d_in, const int* in_sizes, int n_in,
                              void* d_out, int out_size)
{
    const float* x      = (const float*)d_in[0];
    const float* Win    = (const float*)d_in[1];
    const float* bin_   = (const float*)d_in[2];
    const float* Wq     = (const float*)d_in[3];
    const float* bq     = (const float*)d_in[4];
    const float* Wk     = (const float*)d_in[5];
    const float* bk     = (const float*)d_in[6];
    const float* Wv     = (const float*)d_in[7];
    const float* bv     = (const float*)d_in[8];
    const float* Wo     = (const float*)d_in[9];
    const float* bo     = (const float*)d_in[10];
    const float* evs    = (const float*)d_in[11];
    const float* evb    = (const float*)d_in[12];
    const float* W1     = (const float*)d_in[13];
    const float* b1     = (const float*)d_in[14];
    const float* W2     = (const float*)d_in[15];
    const float* b2     = (const float*)d_in[16];
    const float* n1g    = (const float*)d_in[17];
    const float* n1b    = (const float*)d_in[18];
    const float* n2g    = (const float*)d_in[19];
    const float* n2b    = (const float*)d_in[20];
    const float* fng    = (const float*)d_in[21];
    const float* fnb    = (const float*)d_in[22];
    const float* Wout   = (const float*)d_in[23];
    const float* bout   = (const float*)d_in[24];
    float* out = (float*)d_out;

    float *ph, *pln, *pq, *pk, *pv, *pattn, *pff, *punc;
    cudaGetSymbolAddress((void**)&ph,    g_h);
    cudaGetSymbolAddress((void**)&pln,   g_ln);
    cudaGetSymbolAddress((void**)&pq,    g_q);
    cudaGetSymbolAddress((void**)&pk,    g_k);
    cudaGetSymbolAddress((void**)&pv,    g_v);
    cudaGetSymbolAddress((void**)&pattn, g_attn);
    cudaGetSymbolAddress((void**)&pff,   g_ff);
    cudaGetSymbolAddress((void**)&punc,  g_unc);

    const dim3 gD(DMODEL / 64, MTOT / 64);   // N=256 GEMMs
    const dim3 gF(DFF    / 64, MTOT / 64);   // N=1024 GEMMs
    const dim3 gA(SEQ / 64, BATCH * NHEADS); // attention

    // h = x @ Win + bin
    gemm_kernel<0><<<gD, 256>>>(x, Win, bin_, nullptr, ph, DMODEL, DMODEL);

    zero_unc_kernel<<<(BATCH * NHEADS * SEQ + 255) / 256, 256>>>();

    for (int i = 0; i < NLAYERS; i++) {
        const float* Wq_i = Wq + (size_t)i * DMODEL * DMODEL;
        const float* Wk_i = Wk + (size_t)i * DMODEL * DMODEL;
        const float* Wv_i = Wv + (size_t)i * DMODEL * DMODEL;
        const float* Wo_i = Wo + (size_t)i * DMODEL * DMODEL;
        const float* W1_i = W1 + (size_t)i * DMODEL * DFF;
        const float* W2_i = W2 + (size_t)i * DFF * DMODEL;

        // ln1
        ln_kernel<<<MTOT, 256>>>(ph, n1g + i * DMODEL, n1b + i * DMODEL, pln);
        // QKV
        gemm_kernel<0><<<gD, 256>>>(pln, Wq_i, bq + i * DMODEL, nullptr, pq, DMODEL, DMODEL);
        gemm_kernel<0><<<gD, 256>>>(pln, Wk_i, bk + i * DMODEL, nullptr, pk, DMODEL, DMODEL);
        gemm_kernel<0><<<gD, 256>>>(pln, Wv_i, bv + i * DMODEL, nullptr, pv, DMODEL, DMODEL);
        // evidential attention (fused QK^T -> evidence -> EV/denom -> unc)
        attn_kernel<<<gA, 256>>>(pq, pk, pv, pattn, punc, evs, evb, i);
        // h = h + attn @ Wo + bo
        gemm_kernel<1><<<gD, 256>>>(pattn, Wo_i, bo + i * DMODEL, ph, ph, DMODEL, DMODEL);
        // ln2
        ln_kernel<<<MTOT, 256>>>(ph, n2g + i * DMODEL, n2b + i * DMODEL, pln);
        // ff = gelu(ln2 @ W1 + b1)
        gemm_kernel<2><<<gF, 256>>>(pln, W1_i, b1 + i * DFF, nullptr, pff, DFF, DMODEL);
        // h = h + ff @ W2 + b2
        gemm_kernel<1><<<gD, 256>>>(pff, W2_i, b2 + i * DMODEL, ph, ph, DMODEL, DFF);
    }

    // final LN + out projection, written straight into d_out
    ln_kernel<<<MTOT, 256>>>(ph, fng, fnb, pln);
    gemm_kernel<0><<<gD, 256>>>(pln, Wout, bout, nullptr, out, DMODEL, DMODEL);

    // avg_unc + should_abstain appended after `out` region
    if (out_size >= MTOT * DMODEL + 2 * BATCH * NHEADS * SEQ)
        finalize_kernel<<<(BATCH * NHEADS * SEQ + 255) / 256, 256>>>(out);
}

// round 2
// speedup vs baseline: 1.3258x; 1.3258x over previous
#include <cuda_runtime.h>
#include <cuda_bf16.h>
#include <math.h>
#include <stdint.h>

// ---------------- problem constants ----------------
#define NLAYERS 4
#define NHEADS  8
#define DMODEL  256
#define DFF     1024
#define BATCH   2
#define SEQ     2048
#define MTOT    (BATCH * SEQ)   // 4096 rows
#define HD      32              // head dim
#define QKVS    768             // fused QKV row stride

// ---------------- scratch (device globals; no allocation allowed) ----------
__device__ float g_h   [MTOT * DMODEL];
__device__ float g_ln  [MTOT * DMODEL];
__device__ float g_qkv [MTOT * QKVS];
__device__ float g_attn[MTOT * DMODEL];
__device__ float g_ff  [MTOT * DFF];
__device__ float g_unc [BATCH * NHEADS * SEQ];
__device__ float g_bqkv[NLAYERS * QKVS];

// bf16 split weights (hi/lo planes), transposed to [N][K]
__device__ __nv_bfloat16 g_WinH [DMODEL * DMODEL];
__device__ __nv_bfloat16 g_WinL [DMODEL * DMODEL];
__device__ __nv_bfloat16 g_WoutH[DMODEL * DMODEL];
__device__ __nv_bfloat16 g_WoutL[DMODEL * DMODEL];
__device__ __nv_bfloat16 g_WqkvH[NLAYERS * QKVS * DMODEL];
__device__ __nv_bfloat16 g_WqkvL[NLAYERS * QKVS * DMODEL];
__device__ __nv_bfloat16 g_WoH  [NLAYERS * DMODEL * DMODEL];
__device__ __nv_bfloat16 g_WoL  [NLAYERS * DMODEL * DMODEL];
__device__ __nv_bfloat16 g_W1H  [NLAYERS * DFF * DMODEL];
__device__ __nv_bfloat16 g_W1L  [NLAYERS * DFF * DMODEL];
__device__ __nv_bfloat16 g_W2H  [NLAYERS * DMODEL * DFF];
__device__ __nv_bfloat16 g_W2L  [NLAYERS * DMODEL * DFF];

// ---------------- prep: split fp32 weight [K][N] -> bf16 hi/lo [N][K] -------
struct PrepSeg {
    const float* src;
    __nv_bfloat16* hi;
    __nv_bfloat16* lo;
    int K;
    int N;
};
struct PrepArgs { PrepSeg s[26]; };

__global__ void prep_kernel(PrepArgs a)
{
    PrepSeg sg = a.s[blockIdx.y];
    int total = sg.K * sg.N;
    int idx = blockIdx.x * 256 + threadIdx.x;
    if (idx >= total) return;
    int k = idx % sg.K, n = idx / sg.K;
    float v = sg.src[(size_t)k * sg.N + n];
    __nv_bfloat16 h = __float2bfloat16(v);
    float lo = v - __bfloat162float(h);
    sg.hi[idx] = h;
    sg.lo[idx] = __float2bfloat16(lo);
}

// bias concat for fused QKV + zero unc accumulator
__global__ void misc_kernel(const float* __restrict__ bq,
                            const float* __restrict__ bk,
                            const float* __restrict__ bv)
{
    int idx = blockIdx.x * 256 + threadIdx.x;
    if (idx < NLAYERS * QKVS) {
        int l = idx / QKVS, c = idx % QKVS;
        int sec = c >> 8, cc = c & 255;
        const float* s = (sec == 0) ? bq : (sec == 1 ? bk : bv);
        g_bqkv[idx] = s[l * DMODEL + cc];
    }
    int j = idx - NLAYERS * QKVS;
    if (j >= 0 && j < BATCH * NHEADS * SEQ) g_unc[j] = 0.f;
}

// ---------------- layernorm: one block (256 threads) per row ---------------
__global__ void ln_kernel(const float* __restrict__ x,
                          const float* __restrict__ gamma,
                          const float* __restrict__ beta,
                          float* __restrict__ y)
{
    int row = blockIdx.x;
    int tid = threadIdx.x;
    float v = x[(size_t)row * DMODEL + tid];

    __shared__ float red[8];
    float s = v;
    #pragma unroll
    for (int o = 16; o > 0; o >>= 1) s += __shfl_xor_sync(0xffffffffu, s, o);
    if ((tid & 31) == 0) red[tid >> 5] = s;
    __syncthreads();
    float mean = 0.f;
    #pragma unroll
    for (int i = 0; i < 8; i++) mean += red[i];
    mean *= (1.0f / DMODEL);
    __syncthreads();
    float d = v - mean;
    float s2 = d * d;
    #pragma unroll
    for (int o = 16; o > 0; o >>= 1) s2 += __shfl_xor_sync(0xffffffffu, s2, o);
    if ((tid & 31) == 0) red[tid >> 5] = s2;
    __syncthreads();
    float var = 0.f;
    #pragma unroll
    for (int i = 0; i < 8; i++) var += red[i];
    var *= (1.0f / DMODEL);

    y[(size_t)row * DMODEL + tid] = d * rsqrtf(var + 1e-5f) * gamma[tid] + beta[tid];
}

// ---------------- mma helpers ----------------------------------------------
__device__ __forceinline__ uint32_t smem_u32(const void* p)
{
    return (uint32_t)__cvta_generic_to_shared(p);
}

__device__ __forceinline__ void ldsm_x4(uint32_t& r0, uint32_t& r1,
                                        uint32_t& r2, uint32_t& r3, uint32_t addr)
{
    asm volatile("ldmatrix.sync.aligned.m8n8.x4.shared.b16 {%0,%1,%2,%3}, [%4];\n"
                 : "=r"(r0), "=r"(r1), "=r"(r2), "=r"(r3) : "r"(addr));
}

__device__ __forceinline__ void mma_bf16(float* d, const uint32_t* a, const uint32_t* b)
{
    asm volatile(
        "mma.sync.aligned.m16n8k16.row.col.f32.bf16.bf16.f32 "
        "{%0,%1,%2,%3}, {%4,%5,%6,%7}, {%8,%9}, {%0,%1,%2,%3};\n"
        : "+f"(d[0]), "+f"(d[1]), "+f"(d[2]), "+f"(d[3])
        : "r"(a[0]), "r"(a[1]), "r"(a[2]), "r"(a[3]), "r"(b[0]), "r"(b[1]));
}

// ---------------- tensor-core GEMM with fp32-via-bf16 split -----------------
// C[M,N] = epi(A[M,K](fp32) @ B[K,N] + bias), B pre-split as Bh/Bl [N][K] bf16.
// 3-pass: Ah*Bh + Ah*Bl + Al*Bh. Block 128 thr, tile 64x64, BK=32, warps 2x2.
// EPI: 0 bias, 1 bias+residual, 2 bias+exact GELU.
#define SPAD 40   // smem row stride in bf16 elems (80B, 16B-aligned, bank-safe)

template <int EPI>
__global__ void __launch_bounds__(128)
gemmT(const float* __restrict__ A,
      const __nv_bfloat16* __restrict__ Bh, const __nv_bfloat16* __restrict__ Bl,
      const float* __restrict__ bias, const float* __restrict__ res,
      float* __restrict__ C, int K, int ldc)
{
    __shared__ __align__(16) __nv_bfloat16 Ah[64][SPAD];
    __shared__ __align__(16) __nv_bfloat16 Al[64][SPAD];
    __shared__ __align__(16) __nv_bfloat16 Bhs[64][SPAD];
    __shared__ __align__(16) __nv_bfloat16 Bls[64][SPAD];

    int tid = threadIdx.x, lane = tid & 31, warp = tid >> 5;
    int m0 = blockIdx.y * 64, n0 = blockIdx.x * 64;
    int wm = warp >> 1, wn = warp & 1;

    float acc[2][4][4] = {};

    // ldmatrix per-lane address pieces (same pattern for A x4 and B x4-pair)
    int gq = lane >> 3, lr = lane & 7;
    int frow  = (gq & 1) * 8 + lr;   // row within 16
    int fcolh = (gq >> 1) * 8;       // 0 or 8 (k half)

    for (int k0 = 0; k0 < K; k0 += 32) {
        // ---- load + split A tile (64x32 fp32 -> bf16 hi/lo) ----
        #pragma unroll
        for (int e = 0; e < 8; e++) {
            int f = tid + e * 128;
            int m = f >> 4, kp = (f & 15) * 2;
            float2 v = *(const float2*)&A[(size_t)(m0 + m) * K + k0 + kp];
            __nv_bfloat16 h0 = __float2bfloat16(v.x);
            __nv_bfloat16 h1 = __float2bfloat16(v.y);
            __nv_bfloat162 hh; hh.x = h0; hh.y = h1;
            __nv_bfloat162 ll;
            ll.x = __float2bfloat16(v.x - __bfloat162float(h0));
            ll.y = __float2bfloat16(v.y - __bfloat162float(h1));
            *(__nv_bfloat162*)&Ah[m][kp] = hh;
            *(__nv_bfloat162*)&Al[m][kp] = ll;
        }
        // ---- load B tiles (pre-split bf16) ----
        #pragma unroll
        for (int e = 0; e < 8; e++) {
            int f = tid + e * 128;
            int n = f >> 4, kp = (f & 15) * 2;
            *(__nv_bfloat162*)&Bhs[n][kp] = *(const __nv_bfloat162*)&Bh[(size_t)(n0 + n) * K + k0 + kp];
            *(__nv_bfloat162*)&Bls[n][kp] = *(const __nv_bfloat162*)&Bl[(size_t)(n0 + n) * K + k0 + kp];
        }
        __syncthreads();

        #pragma unroll
        for (int s = 0; s < 2; s++) {
            int kb = s * 16;
            uint32_t ah[2][4], al[2][4], bh[4][2], bl[4][2];
            #pragma unroll
            for (int mt = 0; mt < 2; mt++) {
                uint32_t addr = smem_u32(&Ah[wm * 32 + mt * 16 + frow][kb + fcolh]);
                ldsm_x4(ah[mt][0], ah[mt][1], ah[mt][2], ah[mt][3], addr);
                addr = smem_u32(&Al[wm * 32 + mt * 16 + frow][kb + fcolh]);
                ldsm_x4(al[mt][0], al[mt][1], al[mt][2], al[mt][3], addr);
            }
            #pragma unroll
            for (int np = 0; np < 2; np++) {
                uint32_t r0, r1, r2, r3;
                uint32_t addr = smem_u32(&Bhs[wn * 32 + np * 16 + frow][kb + fcolh]);
                ldsm_x4(r0, r1, r2, r3, addr);
                bh[np * 2][0] = r0; bh[np * 2 + 1][0] = r1;
                bh[np * 2][1] = r2; bh[np * 2 + 1][1] = r3;
                addr = smem_u32(&Bls[wn * 32 + np * 16 + frow][kb + fcolh]);
                ldsm_x4(r0, r1, r2, r3, addr);
                bl[np * 2][0] = r0; bl[np * 2 + 1][0] = r1;
                bl[np * 2][1] = r2; bl[np * 2 + 1][1] = r3;
            }
            #pragma unroll
            for (int mt = 0; mt < 2; mt++)
                #pragma unroll
                for (int nt = 0; nt < 4; nt++) {
                    mma_bf16(acc[mt][nt], ah[mt], bh[nt]);   // hi*hi
                    mma_bf16(acc[mt][nt], ah[mt], bl[nt]);   // hi*lo
                    mma_bf16(acc[mt][nt], al[mt], bh[nt]);   // lo*hi
                }
        }
        __syncthreads();
    }

    // ---- epilogue ----
    int gid = lane >> 2, tg = lane & 3;
    #pragma unroll
    for (int mt = 0; mt < 2; mt++) {
        int row0 = m0 + wm * 32 + mt * 16 + gid;
        #pragma unroll
        for (int nt = 0; nt < 4; nt++) {
            int col = n0 + wn * 32 + nt * 8 + tg * 2;
            #pragma unroll
            for (int half = 0; half < 2; half++) {
                int row = row0 + half * 8;
                #pragma unroll
                for (int j = 0; j < 2; j++) {
                    float v = acc[mt][nt][half * 2 + j] + bias[col + j];
                    if (EPI == 1) v += res[(size_t)row * ldc + col + j];
                    if (EPI == 2) v = 0.5f * v * (1.0f + erff(v * 0.70710678118654752f));
                    C[(size_t)row * ldc + col + j] = v;
                }
            }
        }
    }
}

// ---------------- fused evidential attention (SIMT, fused-QKV strides) -----
__global__ void attn_kernel(const float* __restrict__ qkv,
                            float* __restrict__ out,
                            float* __restrict__ unc,
                            const float* __restrict__ ev_scale,
                            const float* __restrict__ ev_bias,
                            int layer)
{
    __shared__ __align__(16) float Qst[32][68];
    __shared__ __align__(16) float Kst[32][68];
    __shared__ __align__(16) float Vs [64][36];
    __shared__ float Es[64][65];

    int tid = threadIdx.x;
    int bh = blockIdx.y;
    int b  = bh >> 3, h = bh & 7;
    int q0 = blockIdx.x * 64;

    float scale = ev_scale[layer];
    float opb   = 1.0f + ev_bias[layer];
    const float inv_sqrt_hd = 0.17677669529663687f;

    const float* base = qkv + (size_t)b * SEQ * QKVS;
    const float* Qb = base + h * HD;
    const float* Kb = base + DMODEL + h * HD;
    const float* Vb = base + 2 * DMODEL + h * HD;

    #pragma unroll
    for (int e = 0; e < 8; e++) {
        int idx = tid + e * 256;
        int r = idx >> 5, c = idx & 31;
        Qst[c][r] = Qb[(size_t)(q0 + r) * QKVS + c];
    }

    int ty = tid >> 4, tx = tid & 15;
    int qq = tid >> 2, dblk = tid & 3;
    int d0 = dblk * 8;

    float EV[8] = {0, 0, 0, 0, 0, 0, 0, 0};
    float ESr = 0.f;

    for (int kb = 0; kb < SEQ; kb += 64) {
        __syncthreads();
        #pragma unroll
        for (int e = 0; e < 8; e++) {
            int idx = tid + e * 256;
            int r = idx >> 5, c = idx & 31;
            Kst[c][r] = Kb[(size_t)(kb + r) * QKVS + c];
            Vs[r][c]  = Vb[(size_t)(kb + r) * QKVS + c];
        }
        __syncthreads();

        float s[4][4] = {};
        #pragma unroll
        for (int kk = 0; kk < HD; kk++) {
            float4 a4 = *(const float4*)&Qst[kk][ty * 4];
            float4 b4 = *(const float4*)&Kst[kk][tx * 4];
            float av[4] = {a4.x, a4.y, a4.z, a4.w};
            float bv[4] = {b4.x, b4.y, b4.z, b4.w};
            #pragma unroll
            for (int i = 0; i < 4; i++)
                #pragma unroll
                for (int j = 0; j < 4; j++)
                    s[i][j] = fmaf(av[i], bv[j], s[i][j]);
        }
        #pragma unroll
        for (int i = 0; i < 4; i++)
            #pragma unroll
            for (int j = 0; j < 4; j++)
                Es[ty * 4 + i][tx * 4 + j] =
                    fmaf(scale, __expf(s[i][j] * inv_sqrt_hd), opb);
        __syncthreads();

        #pragma unroll 4
        for (int k = 0; k < 64; k++) {
            float e = Es[qq][k];
            ESr += e;
            float4 v0 = *(const float4*)&Vs[k][d0];
            float4 v1 = *(const float4*)&Vs[k][d0 + 4];
            EV[0] = fmaf(e, v0.x, EV[0]);
            EV[1] = fmaf(e, v0.y, EV[1]);
            EV[2] = fmaf(e, v0.z, EV[2]);
            EV[3] = fmaf(e, v0.w, EV[3]);
            EV[4] = fmaf(e, v1.x, EV[4]);
            EV[5] = fmaf(e, v1.y, EV[5]);
            EV[6] = fmaf(e, v1.z, EV[6]);
            EV[7] = fmaf(e, v1.w, EV[7]);
        }
    }

    float invd = 1.0f / ESr;
    float* orow = out + (size_t)b * SEQ * DMODEL + (size_t)(q0 + qq) * DMODEL + h * HD + d0;
    #pragma unroll
    for (int j = 0; j < 8; j++) orow[j] = EV[j] * invd;
    if (dblk == 0)
        unc[(size_t)bh * SEQ + q0 + qq] += (float)SEQ * invd;
}

// ---------------- finalize --------------------------------------------------
__global__ void finalize_kernel(float* __restrict__ out)
{
    int i = blockIdx.x * blockDim.x + threadIdx.x;
    if (i < BATCH * NHEADS * SEQ) {
        float a = g_unc[i] * 0.25f;
        out[MTOT * DMODEL + i] = a;
        out[MTOT * DMODEL + BATCH * NHEADS * SEQ + i] = (a > 0.3f) ? 1.0f : 0.0f;
    }
}

// ---------------- launch ----------------------------------------------------
extern "C" void kernel_launch(void* const* d_in, const int* in_sizes, int n_in,
                              void* d_out, int out_size)
{
    const float* x      = (const float*)d_in[0];
    const float* Win    = (const float*)d_in[1];
    const float* bin_   = (const float*)d_in[2];
    const float* Wq     = (const float*)d_in[3];
    const float* bq     = (const float*)d_in[4];
    const float* Wk     = (const float*)d_in[5];
    const float* bk     = (const float*)d_in[6];
    const float* Wv     = (const float*)d_in[7];
    const float* bv     = (const float*)d_in[8];
    const float* Wo     = (const float*)d_in[9];
    const float* bo     = (const float*)d_in[10];
    const float* evs    = (const float*)d_in[11];
    const float* evb    = (const float*)d_in[12];
    const float* W1     = (const float*)d_in[13];
    const float* b1     = (const float*)d_in[14];
    const float* W2     = (const float*)d_in[15];
    const float* b2     = (const float*)d_in[16];
    const float* n1g    = (const float*)d_in[17];
    const float* n1b    = (const float*)d_in[18];
    const float* n2g    = (const float*)d_in[19];
    const float* n2b    = (const float*)d_in[20];
    const float* fng    = (const float*)d_in[21];
    const float* fnb    = (const float*)d_in[22];
    const float* Wout   = (const float*)d_in[23];
    const float* bout   = (const float*)d_in[24];
    float* out = (float*)d_out;

    float *ph, *pln, *pqkv, *pattn, *pff, *punc, *pbqkv;
    cudaGetSymbolAddress((void**)&ph,    g_h);
    cudaGetSymbolAddress((void**)&pln,   g_ln);
    cudaGetSymbolAddress((void**)&pqkv,  g_qkv);
    cudaGetSymbolAddress((void**)&pattn, g_attn);
    cudaGetSymbolAddress((void**)&pff,   g_ff);
    cudaGetSymbolAddress((void**)&punc,  g_unc);
    cudaGetSymbolAddress((void**)&pbqkv, g_bqkv);

    __nv_bfloat16 *WinH, *WinL, *WoutH, *WoutL, *WqkvH, *WqkvL,
                  *WoH, *WoL, *W1H, *W1L, *W2H, *W2L;
    cudaGetSymbolAddress((void**)&WinH,  g_WinH);
    cudaGetSymbolAddress((void**)&WinL,  g_WinL);
    cudaGetSymbolAddress((void**)&WoutH, g_WoutH);
    cudaGetSymbolAddress((void**)&WoutL, g_WoutL);
    cudaGetSymbolAddress((void**)&WqkvH, g_WqkvH);
    cudaGetSymbolAddress((void**)&WqkvL, g_WqkvL);
    cudaGetSymbolAddress((void**)&WoH,   g_WoH);
    cudaGetSymbolAddress((void**)&WoL,   g_WoL);
    cudaGetSymbolAddress((void**)&W1H,   g_W1H);
    cudaGetSymbolAddress((void**)&W1L,   g_W1L);
    cudaGetSymbolAddress((void**)&W2H,   g_W2H);
    cudaGetSymbolAddress((void**)&W2L,   g_W2L);

    // ---- build prep segment table ----
    PrepArgs pa;
    int si = 0;
    pa.s[si++] = { Win,  WinH,  WinL,  DMODEL, DMODEL };
    pa.s[si++] = { Wout, WoutH, WoutL, DMODEL, DMODEL };
    for (int i = 0; i < NLAYERS; i++) {
        size_t qb = (size_t)i * QKVS * DMODEL;
        pa.s[si++] = { Wq + (size_t)i * DMODEL * DMODEL, WqkvH + qb,                   WqkvL + qb,                   DMODEL, DMODEL };
        pa.s[si++] = { Wk + (size_t)i * DMODEL * DMODEL, WqkvH + qb + DMODEL * DMODEL, WqkvL + qb + DMODEL * DMODEL, DMODEL, DMODEL };
        pa.s[si++] = { Wv + (size_t)i * DMODEL * DMODEL, WqkvH + qb + 2 * DMODEL * DMODEL, WqkvL + qb + 2 * DMODEL * DMODEL, DMODEL, DMODEL };
        pa.s[si++] = { Wo + (size_t)i * DMODEL * DMODEL, WoH + (size_t)i * DMODEL * DMODEL, WoL + (size_t)i * DMODEL * DMODEL, DMODEL, DMODEL };
        pa.s[si++] = { W1 + (size_t)i * DMODEL * DFF, W1H + (size_t)i * DFF * DMODEL, W1L + (size_t)i * DFF * DMODEL, DMODEL, DFF };
        pa.s[si++] = { W2 + (size_t)i * DFF * DMODEL, W2H + (size_t)i * DMODEL * DFF, W2L + (size_t)i * DMODEL * DFF, DFF, DMODEL };
    }

    prep_kernel<<<dim3((DFF * DMODEL + 255) / 256, 26), 256>>>(pa);
    misc_kernel<<<(NLAYERS * QKVS + BATCH * NHEADS * SEQ + 255) / 256, 256>>>(bq, bk, bv);

    const dim3 gD(DMODEL / 64, MTOT / 64);   // N=256
    const dim3 gQ(QKVS   / 64, MTOT / 64);   // N=768 fused QKV
    const dim3 gF(DFF    / 64, MTOT / 64);   // N=1024
    const dim3 gA(SEQ / 64, BATCH * NHEADS);

    // h = x @ Win + bin
    gemmT<0><<<gD, 128>>>(x, WinH, WinL, bin_, nullptr, ph, DMODEL, DMODEL);

    for (int i = 0; i < NLAYERS; i++) {
        ln_kernel<<<MTOT, 256>>>(ph, n1g + i * DMODEL, n1b + i * DMODEL, pln);
        // fused QKV: [M,768]
        gemmT<0><<<gQ, 128>>>(pln, WqkvH + (size_t)i * QKVS * DMODEL,
                              WqkvL + (size_t)i * QKVS * DMODEL,
                              pbqkv + i * QKVS, nullptr, pqkv, DMODEL, QKVS);
        attn_kernel<<<gA, 256>>>(pqkv, pattn, punc, evs, evb, i);
        // h = h + attn @ Wo + bo
        gemmT<1><<<gD, 128>>>(pattn, WoH + (size_t)i * DMODEL * DMODEL,
                              WoL + (size_t)i * DMODEL * DMODEL,
                              bo + i * DMODEL, ph, ph, DMODEL, DMODEL);
        ln_kernel<<<MTOT, 256>>>(ph, n2g + i * DMODEL, n2b + i * DMODEL, pln);
        // ff = gelu(ln2 @ W1 + b1)
        gemmT<2><<<gF, 128>>>(pln, W1H + (size_t)i * DFF * DMODEL,
                              W1L + (size_t)i * DFF * DMODEL,
                              b1 + i * DFF, nullptr, pff, DMODEL, DFF);
        // h = h + ff @ W2 + b2
        gemmT<1><<<gD, 128>>>(pff, W2H + (size_t)i * DMODEL * DFF,
                              W2L + (size_t)i * DMODEL * DFF,
                              b2 + i * DMODEL, ph, ph, DFF, DMODEL);
    }

    ln_kernel<<<MTOT, 256>>>(ph, fng, fnb, pln);
    gemmT<0><<<gD, 128>>>(pln, WoutH, WoutL, bout, nullptr, out, DMODEL, DMODEL);

    if (out_size >= MTOT * DMODEL + 2 * BATCH * NHEADS * SEQ)
        finalize_kernel<<<(BATCH * NHEADS * SEQ + 255) / 256, 256>>>(out);
}

// round 3
// speedup vs baseline: 2.8799x; 2.1721x over previous
#include <cuda_runtime.h>
#include <cuda_bf16.h>
#include <math.h>
#include <stdint.h>

// ---------------- problem constants ----------------
#define NLAYERS 4
#define NHEADS  8
#define DMODEL  256
#define DFF     1024
#define BATCH   2
#define SEQ     2048
#define MTOT    (BATCH * SEQ)   // 4096 rows
#define HD      32              // head dim
#define QKVS    768             // fused QKV row stride

// ---------------- scratch (device globals; no allocation allowed) ----------
__device__ float g_h   [MTOT * DMODEL];
__device__ float g_ln  [MTOT * DMODEL];
__device__ float g_qkv [MTOT * QKVS];
__device__ float g_attn[MTOT * DMODEL];
__device__ float g_ff  [MTOT * DFF];
__device__ float g_unc [BATCH * NHEADS * SEQ];
__device__ float g_bqkv[NLAYERS * QKVS];

// bf16 split weights (hi/lo planes), transposed to [N][K]
__device__ __nv_bfloat16 g_WinH [DMODEL * DMODEL];
__device__ __nv_bfloat16 g_WinL [DMODEL * DMODEL];
__device__ __nv_bfloat16 g_WoutH[DMODEL * DMODEL];
__device__ __nv_bfloat16 g_WoutL[DMODEL * DMODEL];
__device__ __nv_bfloat16 g_WqkvH[NLAYERS * QKVS * DMODEL];
__device__ __nv_bfloat16 g_WqkvL[NLAYERS * QKVS * DMODEL];
__device__ __nv_bfloat16 g_WoH  [NLAYERS * DMODEL * DMODEL];
__device__ __nv_bfloat16 g_WoL  [NLAYERS * DMODEL * DMODEL];
__device__ __nv_bfloat16 g_W1H  [NLAYERS * DFF * DMODEL];
__device__ __nv_bfloat16 g_W1L  [NLAYERS * DFF * DMODEL];
__device__ __nv_bfloat16 g_W2H  [NLAYERS * DMODEL * DFF];
__device__ __nv_bfloat16 g_W2L  [NLAYERS * DMODEL * DFF];

// ---------------- prep: split fp32 weight [K][N] -> bf16 hi/lo [N][K] -------
struct PrepSeg {
    const float* src;
    __nv_bfloat16* hi;
    __nv_bfloat16* lo;
    int K;
    int N;
};
struct PrepArgs { PrepSeg s[26]; };

__global__ void prep_kernel(PrepArgs a)
{
    PrepSeg sg = a.s[blockIdx.y];
    int total = sg.K * sg.N;
    int idx = blockIdx.x * 256 + threadIdx.x;
    if (idx >= total) return;
    int k = idx % sg.K, n = idx / sg.K;
    float v = sg.src[(size_t)k * sg.N + n];
    __nv_bfloat16 h = __float2bfloat16(v);
    float lo = v - __bfloat162float(h);
    sg.hi[idx] = h;
    sg.lo[idx] = __float2bfloat16(lo);
}

// bias concat for fused QKV + zero unc accumulator
__global__ void misc_kernel(const float* __restrict__ bq,
                            const float* __restrict__ bk,
                            const float* __restrict__ bv)
{
    int idx = blockIdx.x * 256 + threadIdx.x;
    if (idx < NLAYERS * QKVS) {
        int l = idx / QKVS, c = idx % QKVS;
        int sec = c >> 8, cc = c & 255;
        const float* s = (sec == 0) ? bq : (sec == 1 ? bk : bv);
        g_bqkv[idx] = s[l * DMODEL + cc];
    }
    int j = idx - NLAYERS * QKVS;
    if (j >= 0 && j < BATCH * NHEADS * SEQ) g_unc[j] = 0.f;
}

// ---------------- layernorm: one block (256 threads) per row ---------------
__global__ void ln_kernel(const float* __restrict__ x,
                          const float* __restrict__ gamma,
                          const float* __restrict__ beta,
                          float* __restrict__ y)
{
    int row = blockIdx.x;
    int tid = threadIdx.x;
    float v = x[(size_t)row * DMODEL + tid];

    __shared__ float red[8];
    float s = v;
    #pragma unroll
    for (int o = 16; o > 0; o >>= 1) s += __shfl_xor_sync(0xffffffffu, s, o);
    if ((tid & 31) == 0) red[tid >> 5] = s;
    __syncthreads();
    float mean = 0.f;
    #pragma unroll
    for (int i = 0; i < 8; i++) mean += red[i];
    mean *= (1.0f / DMODEL);
    __syncthreads();
    float d = v - mean;
    float s2 = d * d;
    #pragma unroll
    for (int o = 16; o > 0; o >>= 1) s2 += __shfl_xor_sync(0xffffffffu, s2, o);
    if ((tid & 31) == 0) red[tid >> 5] = s2;
    __syncthreads();
    float var = 0.f;
    #pragma unroll
    for (int i = 0; i < 8; i++) var += red[i];
    var *= (1.0f / DMODEL);

    y[(size_t)row * DMODEL + tid] = d * rsqrtf(var + 1e-5f) * gamma[tid] + beta[tid];
}

// ---------------- mma helpers ----------------------------------------------
__device__ __forceinline__ uint32_t smem_u32(const void* p)
{
    return (uint32_t)__cvta_generic_to_shared(p);
}

__device__ __forceinline__ void ldsm_x4(uint32_t& r0, uint32_t& r1,
                                        uint32_t& r2, uint32_t& r3, uint32_t addr)
{
    asm volatile("ldmatrix.sync.aligned.m8n8.x4.shared.b16 {%0,%1,%2,%3}, [%4];\n"
                 : "=r"(r0), "=r"(r1), "=r"(r2), "=r"(r3) : "r"(addr));
}

__device__ __forceinline__ void mma_bf16(float* d, const uint32_t* a, const uint32_t* b)
{
    asm volatile(
        "mma.sync.aligned.m16n8k16.row.col.f32.bf16.bf16.f32 "
        "{%0,%1,%2,%3}, {%4,%5,%6,%7}, {%8,%9}, {%0,%1,%2,%3};\n"
        : "+f"(d[0]), "+f"(d[1]), "+f"(d[2]), "+f"(d[3])
        : "r"(a[0]), "r"(a[1]), "r"(a[2]), "r"(a[3]), "r"(b[0]), "r"(b[1]));
}

__device__ __forceinline__ void split_bf16x2(float a, float b,
                                             __nv_bfloat162& hi, __nv_bfloat162& lo)
{
    __nv_bfloat16 h0 = __float2bfloat16(a);
    __nv_bfloat16 h1 = __float2bfloat16(b);
    hi.x = h0; hi.y = h1;
    lo.x = __float2bfloat16(a - __bfloat162float(h0));
    lo.y = __float2bfloat16(b - __bfloat162float(h1));
}

// ---------------- tensor-core GEMM with fp32-via-bf16 split -----------------
#define SPAD 40

template <int EPI>
__global__ void __launch_bounds__(128)
gemmT(const float* __restrict__ A,
      const __nv_bfloat16* __restrict__ Bh, const __nv_bfloat16* __restrict__ Bl,
      const float* __restrict__ bias, const float* __restrict__ res,
      float* __restrict__ C, int K, int ldc)
{
    __shared__ __align__(16) __nv_bfloat16 Ah[64][SPAD];
    __shared__ __align__(16) __nv_bfloat16 Al[64][SPAD];
    __shared__ __align__(16) __nv_bfloat16 Bhs[64][SPAD];
    __shared__ __align__(16) __nv_bfloat16 Bls[64][SPAD];

    int tid = threadIdx.x, lane = tid & 31, warp = tid >> 5;
    int m0 = blockIdx.y * 64, n0 = blockIdx.x * 64;
    int wm = warp >> 1, wn = warp & 1;

    float acc[2][4][4] = {};

    int gq = lane >> 3, lr = lane & 7;
    int frow  = (gq & 1) * 8 + lr;
    int fcolh = (gq >> 1) * 8;

    for (int k0 = 0; k0 < K; k0 += 32) {
        #pragma unroll
        for (int e = 0; e < 8; e++) {
            int f = tid + e * 128;
            int m = f >> 4, kp = (f & 15) * 2;
            float2 v = *(const float2*)&A[(size_t)(m0 + m) * K + k0 + kp];
            __nv_bfloat162 hh, ll;
            split_bf16x2(v.x, v.y, hh, ll);
            *(__nv_bfloat162*)&Ah[m][kp] = hh;
            *(__nv_bfloat162*)&Al[m][kp] = ll;
        }
        #pragma unroll
        for (int e = 0; e < 8; e++) {
            int f = tid + e * 128;
            int n = f >> 4, kp = (f & 15) * 2;
            *(__nv_bfloat162*)&Bhs[n][kp] = *(const __nv_bfloat162*)&Bh[(size_t)(n0 + n) * K + k0 + kp];
            *(__nv_bfloat162*)&Bls[n][kp] = *(const __nv_bfloat162*)&Bl[(size_t)(n0 + n) * K + k0 + kp];
        }
        __syncthreads();

        #pragma unroll
        for (int s = 0; s < 2; s++) {
            int kb = s * 16;
            uint32_t ah[2][4], al[2][4], bh[4][2], bl[4][2];
            #pragma unroll
            for (int mt = 0; mt < 2; mt++) {
                uint32_t addr = smem_u32(&Ah[wm * 32 + mt * 16 + frow][kb + fcolh]);
                ldsm_x4(ah[mt][0], ah[mt][1], ah[mt][2], ah[mt][3], addr);
                addr = smem_u32(&Al[wm * 32 + mt * 16 + frow][kb + fcolh]);
                ldsm_x4(al[mt][0], al[mt][1], al[mt][2], al[mt][3], addr);
            }
            #pragma unroll
            for (int np = 0; np < 2; np++) {
                uint32_t r0, r1, r2, r3;
                uint32_t addr = smem_u32(&Bhs[wn * 32 + np * 16 + frow][kb + fcolh]);
                ldsm_x4(r0, r1, r2, r3, addr);
                bh[np * 2][0] = r0; bh[np * 2 + 1][0] = r1;
                bh[np * 2][1] = r2; bh[np * 2 + 1][1] = r3;
                addr = smem_u32(&Bls[wn * 32 + np * 16 + frow][kb + fcolh]);
                ldsm_x4(r0, r1, r2, r3, addr);
                bl[np * 2][0] = r0; bl[np * 2 + 1][0] = r1;
                bl[np * 2][1] = r2; bl[np * 2 + 1][1] = r3;
            }
            #pragma unroll
            for (int mt = 0; mt < 2; mt++)
                #pragma unroll
                for (int nt = 0; nt < 4; nt++) {
                    mma_bf16(acc[mt][nt], ah[mt], bh[nt]);
                    mma_bf16(acc[mt][nt], ah[mt], bl[nt]);
                    mma_bf16(acc[mt][nt], al[mt], bh[nt]);
                }
        }
        __syncthreads();
    }

    int gid = lane >> 2, tg = lane & 3;
    #pragma unroll
    for (int mt = 0; mt < 2; mt++) {
        int row0 = m0 + wm * 32 + mt * 16 + gid;
        #pragma unroll
        for (int nt = 0; nt < 4; nt++) {
            int col = n0 + wn * 32 + nt * 8 + tg * 2;
            #pragma unroll
            for (int half = 0; half < 2; half++) {
                int row = row0 + half * 8;
                #pragma unroll
                for (int j = 0; j < 2; j++) {
                    float v = acc[mt][nt][half * 2 + j] + bias[col + j];
                    if (EPI == 1) v += res[(size_t)row * ldc + col + j];
                    if (EPI == 2) v = 0.5f * v * (1.0f + erff(v * 0.70710678118654752f));
                    C[(size_t)row * ldc + col + j] = v;
                }
            }
        }
    }
}

// ---------------- tensor-core fused evidential attention -------------------
// Block: 128 queries x one (b,h). 256 threads (8 warps). 64-key tiles.
// Scores via split-bf16 mma (QhKh+QhKl+QlKh), e in registers, e split into
// smem bf16 hi/lo, E.V via split mma (EhVh+EhVl+ElVh). Single pass, no max.
#define ATTN_SMEM 77312

__global__ void __launch_bounds__(256)
attn_mma(const float* __restrict__ qkv,
         float* __restrict__ out,
         float* __restrict__ unc,
         const float* __restrict__ ev_scale,
         const float* __restrict__ ev_bias,
         int layer)
{
    extern __shared__ __align__(16) char smraw[];
    __nv_bfloat16* sQh = (__nv_bfloat16*)smraw;          // [128][40]
    __nv_bfloat16* sQl = sQh + 128 * 40;
    __nv_bfloat16* sKh = sQl + 128 * 40;                 // [64][40]
    __nv_bfloat16* sKl = sKh + 64 * 40;
    __nv_bfloat16* sVh = sKl + 64 * 40;                  // [32][72] (transposed)
    __nv_bfloat16* sVl = sVh + 32 * 72;
    __nv_bfloat16* sEh = sVl + 32 * 72;                  // [128][72]
    __nv_bfloat16* sEl = sEh + 128 * 72;
    float* rowsum = (float*)(sEl + 128 * 72);            // [128]

    int tid = threadIdx.x, lane = tid & 31, warp = tid >> 5;
    int bh = blockIdx.y;
    int b = bh >> 3, h = bh & 7;
    int q0 = blockIdx.x * 128;

    float scale = ev_scale[layer];
    float opb   = 1.0f + ev_bias[layer];
    const float inv_sqrt_hd = 0.17677669529663687f;

    const float* base = qkv + (size_t)b * SEQ * QKVS;
    const float* Qb = base + h * HD;
    const float* Kb = base + DMODEL + h * HD;
    const float* Vb = base + 2 * DMODEL + h * HD;

    if (tid < 128) rowsum[tid] = 0.f;

    // load Q tile 128x32, split
    #pragma unroll
    for (int e = 0; e < 8; e++) {
        int f = tid + e * 256;
        int m = f >> 4, kp = (f & 15) * 2;
        float2 v = *(const float2*)&Qb[(size_t)(q0 + m) * QKVS + kp];
        __nv_bfloat162 hh, ll;
        split_bf16x2(v.x, v.y, hh, ll);
        *(__nv_bfloat162*)&sQh[m * 40 + kp] = hh;
        *(__nv_bfloat162*)&sQl[m * 40 + kp] = ll;
    }

    int wm = warp >> 1, wn = warp & 1;         // score phase: 4x2 warp grid
    int gq = lane >> 3, lr = lane & 7;
    int frow = (gq & 1) * 8 + lr, fcolh = (gq >> 1) * 8;
    int gid = lane >> 2, tg = lane & 3;

    float acc_ev[4][4] = {};
    float rs[2][2] = {};

    for (int kb0 = 0; kb0 < SEQ; kb0 += 64) {
        __syncthreads();   // protect E/V/K smem from previous-iter readers (and Q/rowsum on iter 0)
        // load K tile 64x32, split
        #pragma unroll
        for (int e = 0; e < 4; e++) {
            int f = tid + e * 256;
            int m = f >> 4, kp = (f & 15) * 2;
            float2 v = *(const float2*)&Kb[(size_t)(kb0 + m) * QKVS + kp];
            __nv_bfloat162 hh, ll;
            split_bf16x2(v.x, v.y, hh, ll);
            *(__nv_bfloat162*)&sKh[m * 40 + kp] = hh;
            *(__nv_bfloat162*)&sKl[m * 40 + kp] = ll;
        }
        // load V tile 64x32 transposed -> [32][64], split
        #pragma unroll
        for (int e = 0; e < 4; e++) {
            int f = tid + e * 256;
            int key = f >> 4, dp = (f & 15) * 2;
            float2 v = *(const float2*)&Vb[(size_t)(kb0 + key) * QKVS + dp];
            __nv_bfloat16 h0 = __float2bfloat16(v.x);
            __nv_bfloat16 h1 = __float2bfloat16(v.y);
            sVh[dp * 72 + key]       = h0;
            sVh[(dp + 1) * 72 + key] = h1;
            sVl[dp * 72 + key]       = __float2bfloat16(v.x - __bfloat162float(h0));
            sVl[(dp + 1) * 72 + key] = __float2bfloat16(v.y - __bfloat162float(h1));
        }
        __syncthreads();

        // ---- scores: S[128][64] = Q @ K^T (split, 3 passes) ----
        float acc_s[2][4][4] = {};
        #pragma unroll
        for (int s = 0; s < 2; s++) {
            int kb = s * 16;
            uint32_t ah[2][4], al[2][4], bh[4][2], bl[4][2];
            #pragma unroll
            for (int mt = 0; mt < 2; mt++) {
                uint32_t addr = smem_u32(&sQh[(wm * 32 + mt * 16 + frow) * 40 + kb + fcolh]);
                ldsm_x4(ah[mt][0], ah[mt][1], ah[mt][2], ah[mt][3], addr);
                addr = smem_u32(&sQl[(wm * 32 + mt * 16 + frow) * 40 + kb + fcolh]);
                ldsm_x4(al[mt][0], al[mt][1], al[mt][2], al[mt][3], addr);
            }
            #pragma unroll
            for (int np = 0; np < 2; np++) {
                uint32_t r0, r1, r2, r3;
                uint32_t addr = smem_u32(&sKh[(wn * 32 + np * 16 + frow) * 40 + kb + fcolh]);
                ldsm_x4(r0, r1, r2, r3, addr);
                bh[np * 2][0] = r0; bh[np * 2 + 1][0] = r1;
                bh[np * 2][1] = r2; bh[np * 2 + 1][1] = r3;
                addr = smem_u32(&sKl[(wn * 32 + np * 16 + frow) * 40 + kb + fcolh]);
                ldsm_x4(r0, r1, r2, r3, addr);
                bl[np * 2][0] = r0; bl[np * 2 + 1][0] = r1;
                bl[np * 2][1] = r2; bl[np * 2 + 1][1] = r3;
            }
            #pragma unroll
            for (int mt = 0; mt < 2; mt++)
                #pragma unroll
                for (int nt = 0; nt < 4; nt++) {
                    mma_bf16(acc_s[mt][nt], ah[mt], bh[nt]);
                    mma_bf16(acc_s[mt][nt], ah[mt], bl[nt]);
                    mma_bf16(acc_s[mt][nt], al[mt], bh[nt]);
                }
        }

        // ---- e = scale*exp(s/sqrt(hd)) + 1 + bias; rowsum partials; split to smem ----
        #pragma unroll
        for (int mt = 0; mt < 2; mt++) {
            #pragma unroll
            for (int half = 0; half < 2; half++) {
                int row = wm * 32 + mt * 16 + half * 8 + gid;
                #pragma unroll
                for (int nt = 0; nt < 4; nt++) {
                    float e0 = fmaf(scale, __expf(acc_s[mt][nt][half * 2 + 0] * inv_sqrt_hd), opb);
                    float e1 = fmaf(scale, __expf(acc_s[mt][nt][half * 2 + 1] * inv_sqrt_hd), opb);
                    rs[mt][half] += e0 + e1;
                    int col = wn * 32 + nt * 8 + tg * 2;
                    __nv_bfloat162 hh, ll;
                    split_bf16x2(e0, e1, hh, ll);
                    *(__nv_bfloat162*)&sEh[row * 72 + col] = hh;
                    *(__nv_bfloat162*)&sEl[row * 72 + col] = ll;
                }
            }
        }
        __syncthreads();

        // ---- EV accumulate: [128][32] += E[128][64] @ V[64][32] (split, 3 passes) ----
        // warp w owns rows [w*16, w*16+16)
        #pragma unroll
        for (int kb = 0; kb < 64; kb += 16) {
            uint32_t eh[4], el[4], vh[4][2], vl[4][2];
            uint32_t addr = smem_u32(&sEh[(warp * 16 + frow) * 72 + kb + fcolh]);
            ldsm_x4(eh[0], eh[1], eh[2], eh[3], addr);
            addr = smem_u32(&sEl[(warp * 16 + frow) * 72 + kb + fcolh]);
            ldsm_x4(el[0], el[1], el[2], el[3], addr);
            #pragma unroll
            for (int np = 0; np < 2; np++) {
                uint32_t r0, r1, r2, r3;
                addr = smem_u32(&sVh[(np * 16 + frow) * 72 + kb + fcolh]);
                ldsm_x4(r0, r1, r2, r3, addr);
                vh[np * 2][0] = r0; vh[np * 2 + 1][0] = r1;
                vh[np * 2][1] = r2; vh[np * 2 + 1][1] = r3;
                addr = smem_u32(&sVl[(np * 16 + frow) * 72 + kb + fcolh]);
                ldsm_x4(r0, r1, r2, r3, addr);
                vl[np * 2][0] = r0; vl[np * 2 + 1][0] = r1;
                vl[np * 2][1] = r2; vl[np * 2 + 1][1] = r3;
            }
            #pragma unroll
            for (int nt = 0; nt < 4; nt++) {
                mma_bf16(acc_ev[nt], eh, vh[nt]);
                mma_bf16(acc_ev[nt], eh, vl[nt]);
                mma_bf16(acc_ev[nt], el, vh[nt]);
            }
        }
    }

    // ---- rowsum: reduce over quad lanes, combine wn warps via smem atomics ----
    #pragma unroll
    for (int mt = 0; mt < 2; mt++)
        #pragma unroll
        for (int half = 0; half < 2; half++) {
            float v = rs[mt][half];
            v += __shfl_xor_sync(0xffffffffu, v, 1);
            v += __shfl_xor_sync(0xffffffffu, v, 2);
            if (tg == 0)
                atomicAdd(&rowsum[wm * 32 + mt * 16 + half * 8 + gid], v);
        }
    __syncthreads();

    // ---- epilogue: out = EV/denom, unc += L/denom ----
    #pragma unroll
    for (int half = 0; half < 2; half++) {
        int row = warp * 16 + half * 8 + gid;
        float invd = 1.0f / rowsum[row];
        float* orow = out + (size_t)b * SEQ * DMODEL + (size_t)(q0 + row) * DMODEL + h * HD;
        #pragma unroll
        for (int nt = 0; nt < 4; nt++) {
            int col = nt * 8 + tg * 2;
            orow[col]     = acc_ev[nt][half * 2 + 0] * invd;
            orow[col + 1] = acc_ev[nt][half * 2 + 1] * invd;
        }
        if (tg == 0)
            unc[(size_t)bh * SEQ + q0 + row] += (float)SEQ * invd;
    }
}

// ---------------- finalize --------------------------------------------------
__global__ void finalize_kernel(float* __restrict__ out)
{
    int i = blockIdx.x * blockDim.x + threadIdx.x;
    if (i < BATCH * NHEADS * SEQ) {
        float a = g_unc[i] * 0.25f;
        out[MTOT * DMODEL + i] = a;
        out[MTOT * DMODEL + BATCH * NHEADS * SEQ + i] = (a > 0.3f) ? 1.0f : 0.0f;
    }
}

// ---------------- launch ----------------------------------------------------
extern "C" void kernel_launch(void* const* d_in, const int* in_sizes, int n_in,
                              void* d_out, int out_size)
{
    const float* x      = (const float*)d_in[0];
    const float* Win    = (const float*)d_in[1];
    const float* bin_   = (const float*)d_in[2];
    const float* Wq     = (const float*)d_in[3];
    const float* bq     = (const float*)d_in[4];
    const float* Wk     = (const float*)d_in[5];
    const float* bk     = (const float*)d_in[6];
    const float* Wv     = (const float*)d_in[7];
    const float* bv     = (const float*)d_in[8];
    const float* Wo     = (const float*)d_in[9];
    const float* bo     = (const float*)d_in[10];
    const float* evs    = (const float*)d_in[11];
    const float* evb    = (const float*)d_in[12];
    const float* W1     = (const float*)d_in[13];
    const float* b1     = (const float*)d_in[14];
    const float* W2     = (const float*)d_in[15];
    const float* b2     = (const float*)d_in[16];
    const float* n1g    = (const float*)d_in[17];
    const float* n1b    = (const float*)d_in[18];
    const float* n2g    = (const float*)d_in[19];
    const float* n2b    = (const float*)d_in[20];
    const float* fng    = (const float*)d_in[21];
    const float* fnb    = (const float*)d_in[22];
    const float* Wout   = (const float*)d_in[23];
    const float* bout   = (const float*)d_in[24];
    float* out = (float*)d_out;

    float *ph, *pln, *pqkv, *pattn, *pff, *punc, *pbqkv;
    cudaGetSymbolAddress((void**)&ph,    g_h);
    cudaGetSymbolAddress((void**)&pln,   g_ln);
    cudaGetSymbolAddress((void**)&pqkv,  g_qkv);
    cudaGetSymbolAddress((void**)&pattn, g_attn);
    cudaGetSymbolAddress((void**)&pff,   g_ff);
    cudaGetSymbolAddress((void**)&punc,  g_unc);
    cudaGetSymbolAddress((void**)&pbqkv, g_bqkv);

    __nv_bfloat16 *WinH, *WinL, *WoutH, *WoutL, *WqkvH, *WqkvL,
                  *WoH, *WoL, *W1H, *W1L, *W2H, *W2L;
    cudaGetSymbolAddress((void**)&WinH,  g_WinH);
    cudaGetSymbolAddress((void**)&WinL,  g_WinL);
    cudaGetSymbolAddress((void**)&WoutH, g_WoutH);
    cudaGetSymbolAddress((void**)&WoutL, g_WoutL);
    cudaGetSymbolAddress((void**)&WqkvH, g_WqkvH);
    cudaGetSymbolAddress((void**)&WqkvL, g_WqkvL);
    cudaGetSymbolAddress((void**)&WoH,   g_WoH);
    cudaGetSymbolAddress((void**)&WoL,   g_WoL);
    cudaGetSymbolAddress((void**)&W1H,   g_W1H);
    cudaGetSymbolAddress((void**)&W1L,   g_W1L);
    cudaGetSymbolAddress((void**)&W2H,   g_W2H);
    cudaGetSymbolAddress((void**)&W2L,   g_W2L);

    static bool attr_done = false;
    if (!attr_done) {
        cudaFuncSetAttribute(attn_mma, cudaFuncAttributeMaxDynamicSharedMemorySize, ATTN_SMEM);
        attr_done = true;
    }

    // ---- build prep segment table ----
    PrepArgs pa;
    int si = 0;
    pa.s[si++] = { Win,  WinH,  WinL,  DMODEL, DMODEL };
    pa.s[si++] = { Wout, WoutH, WoutL, DMODEL, DMODEL };
    for (int i = 0; i < NLAYERS; i++) {
        size_t qb = (size_t)i * QKVS * DMODEL;
        pa.s[si++] = { Wq + (size_t)i * DMODEL * DMODEL, WqkvH + qb,                   WqkvL + qb,                   DMODEL, DMODEL };
        pa.s[si++] = { Wk + (size_t)i * DMODEL * DMODEL, WqkvH + qb + DMODEL * DMODEL, WqkvL + qb + DMODEL * DMODEL, DMODEL, DMODEL };
        pa.s[si++] = { Wv + (size_t)i * DMODEL * DMODEL, WqkvH + qb + 2 * DMODEL * DMODEL, WqkvL + qb + 2 * DMODEL * DMODEL, DMODEL, DMODEL };
        pa.s[si++] = { Wo + (size_t)i * DMODEL * DMODEL, WoH + (size_t)i * DMODEL * DMODEL, WoL + (size_t)i * DMODEL * DMODEL, DMODEL, DMODEL };
        pa.s[si++] = { W1 + (size_t)i * DMODEL * DFF, W1H + (size_t)i * DFF * DMODEL, W1L + (size_t)i * DFF * DMODEL, DMODEL, DFF };
        pa.s[si++] = { W2 + (size_t)i * DFF * DMODEL, W2H + (size_t)i * DMODEL * DFF, W2L + (size_t)i * DMODEL * DFF, DFF, DMODEL };
    }

    prep_kernel<<<dim3((DFF * DMODEL + 255) / 256, 26), 256>>>(pa);
    misc_kernel<<<(NLAYERS * QKVS + BATCH * NHEADS * SEQ + 255) / 256, 256>>>(bq, bk, bv);

    const dim3 gD(DMODEL / 64, MTOT / 64);
    const dim3 gQ(QKVS   / 64, MTOT / 64);
    const dim3 gF(DFF    / 64, MTOT / 64);
    const dim3 gA(SEQ / 128, BATCH * NHEADS);

    gemmT<0><<<gD, 128>>>(x, WinH, WinL, bin_, nullptr, ph, DMODEL, DMODEL);

    for (int i = 0; i < NLAYERS; i++) {
        ln_kernel<<<MTOT, 256>>>(ph, n1g + i * DMODEL, n1b + i * DMODEL, pln);
        gemmT<0><<<gQ, 128>>>(pln, WqkvH + (size_t)i * QKVS * DMODEL,
                              WqkvL + (size_t)i * QKVS * DMODEL,
                              pbqkv + i * QKVS, nullptr, pqkv, DMODEL, QKVS);
        attn_mma<<<gA, 256, ATTN_SMEM>>>(pqkv, pattn, punc, evs, evb, i);
        gemmT<1><<<gD, 128>>>(pattn, WoH + (size_t)i * DMODEL * DMODEL,
                              WoL + (size_t)i * DMODEL * DMODEL,
                              bo + i * DMODEL, ph, ph, DMODEL, DMODEL);
        ln_kernel<<<MTOT, 256>>>(ph, n2g + i * DMODEL, n2b + i * DMODEL, pln);
        gemmT<2><<<gF, 128>>>(pln, W1H + (size_t)i * DFF * DMODEL,
                              W1L + (size_t)i * DFF * DMODEL,
                              b1 + i * DFF, nullptr, pff, DMODEL, DFF);
        gemmT<1><<<gD, 128>>>(pff, W2H + (size_t)i * DMODEL * DFF,
                              W2L + (size_t)i * DMODEL * DFF,
                              b2 + i * DMODEL, ph, ph, DFF, DMODEL);
    }

    ln_kernel<<<MTOT, 256>>>(ph, fng, fnb, pln);
    gemmT<0><<<gD, 128>>>(pln, WoutH, WoutL, bout, nullptr, out, DMODEL, DMODEL);

    if (out_size >= MTOT * DMODEL + 2 * BATCH * NHEADS * SEQ)
        finalize_kernel<<<(BATCH * NHEADS * SEQ + 255) / 256, 256>>>(out);
}

// round 4
// speedup vs baseline: 3.0264x; 1.0509x over previous
#include <cuda_runtime.h>
#include <cuda_bf16.h>
#include <math.h>
#include <stdint.h>

// ---------------- problem constants ----------------
#define NLAYERS 4
#define NHEADS  8
#define DMODEL  256
#define DFF     1024
#define BATCH   2
#define SEQ     2048
#define MTOT    (BATCH * SEQ)   // 4096 rows
#define HD      32              // head dim
#define QKVS    768             // fused QKV row stride

// ---------------- scratch (device globals; no allocation allowed) ----------
__device__ float g_h   [MTOT * DMODEL];          // residual stream (fp32)
__device__ float g_unc [BATCH * NHEADS * SEQ];
__device__ float g_bqkv[NLAYERS * QKVS];

// split bf16 activation planes
__device__ __nv_bfloat16 g_xH   [MTOT * DMODEL];
__device__ __nv_bfloat16 g_xL   [MTOT * DMODEL];
__device__ __nv_bfloat16 g_lnH  [MTOT * DMODEL];
__device__ __nv_bfloat16 g_lnL  [MTOT * DMODEL];
__device__ __nv_bfloat16 g_qkvH [MTOT * QKVS];
__device__ __nv_bfloat16 g_qkvL [MTOT * QKVS];
__device__ __nv_bfloat16 g_attnH[MTOT * DMODEL];
__device__ __nv_bfloat16 g_attnL[MTOT * DMODEL];
__device__ __nv_bfloat16 g_ffH  [MTOT * DFF];
__device__ __nv_bfloat16 g_ffL  [MTOT * DFF];

// bf16 split weights (hi/lo planes), transposed to [N][K]
__device__ __nv_bfloat16 g_WinH [DMODEL * DMODEL];
__device__ __nv_bfloat16 g_WinL [DMODEL * DMODEL];
__device__ __nv_bfloat16 g_WoutH[DMODEL * DMODEL];
__device__ __nv_bfloat16 g_WoutL[DMODEL * DMODEL];
__device__ __nv_bfloat16 g_WqkvH[NLAYERS * QKVS * DMODEL];
__device__ __nv_bfloat16 g_WqkvL[NLAYERS * QKVS * DMODEL];
__device__ __nv_bfloat16 g_WoH  [NLAYERS * DMODEL * DMODEL];
__device__ __nv_bfloat16 g_WoL  [NLAYERS * DMODEL * DMODEL];
__device__ __nv_bfloat16 g_W1H  [NLAYERS * DFF * DMODEL];
__device__ __nv_bfloat16 g_W1L  [NLAYERS * DFF * DMODEL];
__device__ __nv_bfloat16 g_W2H  [NLAYERS * DMODEL * DFF];
__device__ __nv_bfloat16 g_W2L  [NLAYERS * DMODEL * DFF];

// ---------------- prep: split fp32 weight [K][N] -> bf16 hi/lo [N][K] -------
struct PrepSeg {
    const float* src;
    __nv_bfloat16* hi;
    __nv_bfloat16* lo;
    int K;
    int N;
};
struct PrepArgs { PrepSeg s[26]; };

__global__ void prep_kernel(PrepArgs a)
{
    PrepSeg sg = a.s[blockIdx.y];
    int total = sg.K * sg.N;
    int idx = blockIdx.x * 256 + threadIdx.x;
    if (idx >= total) return;
    int k = idx % sg.K, n = idx / sg.K;
    float v = sg.src[(size_t)k * sg.N + n];
    __nv_bfloat16 h = __float2bfloat16(v);
    sg.hi[idx] = h;
    sg.lo[idx] = __float2bfloat16(v - __bfloat162float(h));
}

// split input activation x (same layout) + bias concat + zero unc
__global__ void splitx_kernel(const float* __restrict__ x)
{
    int idx = blockIdx.x * 256 + threadIdx.x;
    if (idx < MTOT * DMODEL) {
        float v = x[idx];
        __nv_bfloat16 h = __float2bfloat16(v);
        g_xH[idx] = h;
        g_xL[idx] = __float2bfloat16(v - __bfloat162float(h));
    }
}

__global__ void misc_kernel(const float* __restrict__ bq,
                            const float* __restrict__ bk,
                            const float* __restrict__ bv)
{
    int idx = blockIdx.x * 256 + threadIdx.x;
    if (idx < NLAYERS * QKVS) {
        int l = idx / QKVS, c = idx % QKVS;
        int sec = c >> 8, cc = c & 255;
        const float* s = (sec == 0) ? bq : (sec == 1 ? bk : bv);
        g_bqkv[idx] = s[l * DMODEL + cc];
    }
    int j = idx - NLAYERS * QKVS;
    if (j >= 0 && j < BATCH * NHEADS * SEQ) g_unc[j] = 0.f;
}

// ---------------- layernorm: one block per row; writes SPLIT bf16 ----------
__global__ void ln_kernel(const float* __restrict__ x,
                          const float* __restrict__ gamma,
                          const float* __restrict__ beta,
                          __nv_bfloat16* __restrict__ yH,
                          __nv_bfloat16* __restrict__ yL)
{
    int row = blockIdx.x;
    int tid = threadIdx.x;
    float v = x[(size_t)row * DMODEL + tid];

    __shared__ float red[8];
    float s = v;
    #pragma unroll
    for (int o = 16; o > 0; o >>= 1) s += __shfl_xor_sync(0xffffffffu, s, o);
    if ((tid & 31) == 0) red[tid >> 5] = s;
    __syncthreads();
    float mean = 0.f;
    #pragma unroll
    for (int i = 0; i < 8; i++) mean += red[i];
    mean *= (1.0f / DMODEL);
    __syncthreads();
    float d = v - mean;
    float s2 = d * d;
    #pragma unroll
    for (int o = 16; o > 0; o >>= 1) s2 += __shfl_xor_sync(0xffffffffu, s2, o);
    if ((tid & 31) == 0) red[tid >> 5] = s2;
    __syncthreads();
    float var = 0.f;
    #pragma unroll
    for (int i = 0; i < 8; i++) var += red[i];
    var *= (1.0f / DMODEL);

    float y = d * rsqrtf(var + 1e-5f) * gamma[tid] + beta[tid];
    __nv_bfloat16 h = __float2bfloat16(y);
    yH[(size_t)row * DMODEL + tid] = h;
    yL[(size_t)row * DMODEL + tid] = __float2bfloat16(y - __bfloat162float(h));
}

// ---------------- mma / cp.async helpers ------------------------------------
__device__ __forceinline__ uint32_t smem_u32(const void* p)
{
    return (uint32_t)__cvta_generic_to_shared(p);
}

__device__ __forceinline__ void ldsm_x4(uint32_t& r0, uint32_t& r1,
                                        uint32_t& r2, uint32_t& r3, uint32_t addr)
{
    asm volatile("ldmatrix.sync.aligned.m8n8.x4.shared.b16 {%0,%1,%2,%3}, [%4];\n"
                 : "=r"(r0), "=r"(r1), "=r"(r2), "=r"(r3) : "r"(addr));
}

__device__ __forceinline__ void mma_bf16(float* d, const uint32_t* a, const uint32_t* b)
{
    asm volatile(
        "mma.sync.aligned.m16n8k16.row.col.f32.bf16.bf16.f32 "
        "{%0,%1,%2,%3}, {%4,%5,%6,%7}, {%8,%9}, {%0,%1,%2,%3};\n"
        : "+f"(d[0]), "+f"(d[1]), "+f"(d[2]), "+f"(d[3])
        : "r"(a[0]), "r"(a[1]), "r"(a[2]), "r"(a[3]), "r"(b[0]), "r"(b[1]));
}

__device__ __forceinline__ void split_bf16x2(float a, float b,
                                             __nv_bfloat162& hi, __nv_bfloat162& lo)
{
    __nv_bfloat16 h0 = __float2bfloat16(a);
    __nv_bfloat16 h1 = __float2bfloat16(b);
    hi.x = h0; hi.y = h1;
    lo.x = __float2bfloat16(a - __bfloat162float(h0));
    lo.y = __float2bfloat16(b - __bfloat162float(h1));
}

__device__ __forceinline__ void cp16(void* dst, const void* src)
{
    asm volatile("cp.async.cg.shared.global [%0], [%1], 16;\n"
                 :: "r"(smem_u32(dst)), "l"(src));
}
__device__ __forceinline__ void cp_commit()
{
    asm volatile("cp.async.commit_group;\n");
}
template <int N>
__device__ __forceinline__ void cp_wait()
{
    asm volatile("cp.async.wait_group %0;\n" :: "n"(N));
}

// ---------------- pipelined pre-split bf16 GEMM -----------------------------
// C[M,N] = epi(A @ B + bias); A as Ah/Al [M][K], B as Bh/Bl [N][K] bf16.
// 3-pass split mma. Tile 128x64, BK=32, 256 threads, 2-stage cp.async.
// EPI: 0 bias, 1 bias+res, 2 bias+exact GELU. SPLIT: write Ch/Cl bf16 else C fp32.
#define GASZ (128 * 40)
#define GBSZ (64 * 40)
#define GSTG (2 * GASZ + 2 * GBSZ)           // elems per stage
#define GEMM_SMEM (2 * GSTG * 2)             // bytes = 61440

template <int EPI, int SPLIT>
__global__ void __launch_bounds__(256)
gemm2(const __nv_bfloat16* __restrict__ Ah_, const __nv_bfloat16* __restrict__ Al_,
      const __nv_bfloat16* __restrict__ Bh_, const __nv_bfloat16* __restrict__ Bl_,
      const float* __restrict__ bias, const float* __restrict__ res,
      float* __restrict__ C, __nv_bfloat16* __restrict__ Ch, __nv_bfloat16* __restrict__ Cl,
      int K, int ldc)
{
    extern __shared__ __align__(16) __nv_bfloat16 sm[];

    int tid = threadIdx.x, lane = tid & 31, warp = tid >> 5;
    int m0 = blockIdx.y * 128, n0 = blockIdx.x * 64;
    int wm = warp >> 1, wn = warp & 1;

    int gq = lane >> 3, lr = lane & 7;
    int frow  = (gq & 1) * 8 + lr;
    int fcolh = (gq >> 1) * 8;

    float acc[2][4][4] = {};

    // per-thread load assignment (chunk = 16B = 8 bf16)
    int arow0 = tid >> 2,           acol = (tid & 3) * 8;       // A chunk 0
    int arow1 = (tid + 256) >> 2;                               // A chunk 1
    int brow  = tid >> 2;                                       // B chunk

    auto load_stage = [&](int stage, int k0) {
        __nv_bfloat16* base = sm + stage * GSTG;
        cp16(&base[arow0 * 40 + acol],               &Ah_[(size_t)(m0 + arow0) * K + k0 + acol]);
        cp16(&base[arow1 * 40 + acol],               &Ah_[(size_t)(m0 + arow1) * K + k0 + acol]);
        cp16(&base[GASZ + arow0 * 40 + acol],        &Al_[(size_t)(m0 + arow0) * K + k0 + acol]);
        cp16(&base[GASZ + arow1 * 40 + acol],        &Al_[(size_t)(m0 + arow1) * K + k0 + acol]);
        cp16(&base[2 * GASZ + brow * 40 + acol],     &Bh_[(size_t)(n0 + brow) * K + k0 + acol]);
        cp16(&base[2 * GASZ + GBSZ + brow * 40 + acol], &Bl_[(size_t)(n0 + brow) * K + k0 + acol]);
    };

    load_stage(0, 0);
    cp_commit();

    int kiters = K >> 5;
    for (int it = 0; it < kiters; it++) {
        int stage = it & 1;
        if (it + 1 < kiters) {
            load_stage(stage ^ 1, (it + 1) * 32);
            cp_commit();
            cp_wait<1>();
        } else {
            cp_wait<0>();
        }
        __syncthreads();

        __nv_bfloat16* sAh = sm + stage * GSTG;
        __nv_bfloat16* sAl = sAh + GASZ;
        __nv_bfloat16* sBh = sAh + 2 * GASZ;
        __nv_bfloat16* sBl = sBh + GBSZ;

        #pragma unroll
        for (int s = 0; s < 2; s++) {
            int kb = s * 16;
            uint32_t ah[2][4], al[2][4], bh[4][2], bl[4][2];
            #pragma unroll
            for (int mt = 0; mt < 2; mt++) {
                uint32_t addr = smem_u32(&sAh[(wm * 32 + mt * 16 + frow) * 40 + kb + fcolh]);
                ldsm_x4(ah[mt][0], ah[mt][1], ah[mt][2], ah[mt][3], addr);
                addr = smem_u32(&sAl[(wm * 32 + mt * 16 + frow) * 40 + kb + fcolh]);
                ldsm_x4(al[mt][0], al[mt][1], al[mt][2], al[mt][3], addr);
            }
            #pragma unroll
            for (int np = 0; np < 2; np++) {
                uint32_t r0, r1, r2, r3;
                uint32_t addr = smem_u32(&sBh[(wn * 32 + np * 16 + frow) * 40 + kb + fcolh]);
                ldsm_x4(r0, r1, r2, r3, addr);
                bh[np * 2][0] = r0; bh[np * 2 + 1][0] = r1;
                bh[np * 2][1] = r2; bh[np * 2 + 1][1] = r3;
                addr = smem_u32(&sBl[(wn * 32 + np * 16 + frow) * 40 + kb + fcolh]);
                ldsm_x4(r0, r1, r2, r3, addr);
                bl[np * 2][0] = r0; bl[np * 2 + 1][0] = r1;
                bl[np * 2][1] = r2; bl[np * 2 + 1][1] = r3;
            }
            #pragma unroll
            for (int mt = 0; mt < 2; mt++)
                #pragma unroll
                for (int nt = 0; nt < 4; nt++) {
                    mma_bf16(acc[mt][nt], ah[mt], bh[nt]);
                    mma_bf16(acc[mt][nt], ah[mt], bl[nt]);
                    mma_bf16(acc[mt][nt], al[mt], bh[nt]);
                }
        }
        __syncthreads();
    }

    // ---- epilogue ----
    int gid = lane >> 2, tg = lane & 3;
    #pragma unroll
    for (int mt = 0; mt < 2; mt++) {
        int row0 = m0 + wm * 32 + mt * 16 + gid;
        #pragma unroll
        for (int nt = 0; nt < 4; nt++) {
            int col = n0 + wn * 32 + nt * 8 + tg * 2;
            #pragma unroll
            for (int half = 0; half < 2; half++) {
                int row = row0 + half * 8;
                float v0 = acc[mt][nt][half * 2 + 0] + bias[col];
                float v1 = acc[mt][nt][half * 2 + 1] + bias[col + 1];
                if (EPI == 1) {
                    v0 += res[(size_t)row * ldc + col];
                    v1 += res[(size_t)row * ldc + col + 1];
                }
                if (EPI == 2) {
                    v0 = 0.5f * v0 * (1.0f + erff(v0 * 0.70710678118654752f));
                    v1 = 0.5f * v1 * (1.0f + erff(v1 * 0.70710678118654752f));
                }
                if (SPLIT) {
                    __nv_bfloat162 hh, ll;
                    split_bf16x2(v0, v1, hh, ll);
                    *(__nv_bfloat162*)&Ch[(size_t)row * ldc + col] = hh;
                    *(__nv_bfloat162*)&Cl[(size_t)row * ldc + col] = ll;
                } else {
                    float2 f2; f2.x = v0; f2.y = v1;
                    *(float2*)&C[(size_t)row * ldc + col] = f2;
                }
            }
        }
    }
}

// ---------------- tensor-core fused evidential attention -------------------
// Consumes pre-split bf16 QKV; produces split bf16 attn output.
#define ATTN_SMEM 77312

__global__ void __launch_bounds__(256)
attn_mma(const __nv_bfloat16* __restrict__ qkvH,
         const __nv_bfloat16* __restrict__ qkvL,
         __nv_bfloat16* __restrict__ outH,
         __nv_bfloat16* __restrict__ outL,
         float* __restrict__ unc,
         const float* __restrict__ ev_scale,
         const float* __restrict__ ev_bias,
         int layer)
{
    extern __shared__ __align__(16) char smraw[];
    __nv_bfloat16* sQh = (__nv_bfloat16*)smraw;          // [128][40]
    __nv_bfloat16* sQl = sQh + 128 * 40;
    __nv_bfloat16* sKh = sQl + 128 * 40;                 // [64][40]
    __nv_bfloat16* sKl = sKh + 64 * 40;
    __nv_bfloat16* sVh = sKl + 64 * 40;                  // [32][72] transposed
    __nv_bfloat16* sVl = sVh + 32 * 72;
    __nv_bfloat16* sEh = sVl + 32 * 72;                  // [128][72]
    __nv_bfloat16* sEl = sEh + 128 * 72;
    float* rowsum = (float*)(sEl + 128 * 72);            // [128]

    int tid = threadIdx.x, lane = tid & 31, warp = tid >> 5;
    int bh = blockIdx.y;
    int b = bh >> 3, h = bh & 7;
    int q0 = blockIdx.x * 128;

    float scale = ev_scale[layer];
    float opb   = 1.0f + ev_bias[layer];
    const float inv_sqrt_hd = 0.17677669529663687f;

    const __nv_bfloat16* QbH = qkvH + (size_t)b * SEQ * QKVS + h * HD;
    const __nv_bfloat16* QbL = qkvL + (size_t)b * SEQ * QKVS + h * HD;
    const __nv_bfloat16* KbH = QbH + DMODEL;
    const __nv_bfloat16* KbL = QbL + DMODEL;
    const __nv_bfloat16* VbH = QbH + 2 * DMODEL;
    const __nv_bfloat16* VbL = QbL + 2 * DMODEL;

    if (tid < 128) rowsum[tid] = 0.f;

    // load Q tile 128x32 (both planes), 16B chunks
    #pragma unroll
    for (int e = 0; e < 2; e++) {
        int f = tid + e * 256;
        int m = f >> 2, c8 = (f & 3) * 8;
        *(uint4*)&sQh[m * 40 + c8] = *(const uint4*)&QbH[(size_t)(q0 + m) * QKVS + c8];
        *(uint4*)&sQl[m * 40 + c8] = *(const uint4*)&QbL[(size_t)(q0 + m) * QKVS + c8];
    }

    int wm = warp >> 1, wn = warp & 1;
    int gq = lane >> 3, lr = lane & 7;
    int frow = (gq & 1) * 8 + lr, fcolh = (gq >> 1) * 8;
    int gid = lane >> 2, tg = lane & 3;

    float acc_ev[4][4] = {};
    float rs[2][2] = {};

    for (int kb0 = 0; kb0 < SEQ; kb0 += 64) {
        __syncthreads();
        // K tile 64x32 both planes
        {
            int m = tid >> 2, c8 = (tid & 3) * 8;
            *(uint4*)&sKh[m * 40 + c8] = *(const uint4*)&KbH[(size_t)(kb0 + m) * QKVS + c8];
            *(uint4*)&sKl[m * 40 + c8] = *(const uint4*)&KbL[(size_t)(kb0 + m) * QKVS + c8];
        }
        // V tile 64x32 -> transposed [32][64+pad], both planes (bf162 pairs)
        #pragma unroll
        for (int e = 0; e < 4; e++) {
            int f = tid + e * 256;
            int key = f >> 4, dp = (f & 15) * 2;
            __nv_bfloat162 vh = *(const __nv_bfloat162*)&VbH[(size_t)(kb0 + key) * QKVS + dp];
            __nv_bfloat162 vl = *(const __nv_bfloat162*)&VbL[(size_t)(kb0 + key) * QKVS + dp];
            sVh[dp * 72 + key]       = vh.x;
            sVh[(dp + 1) * 72 + key] = vh.y;
            sVl[dp * 72 + key]       = vl.x;
            sVl[(dp + 1) * 72 + key] = vl.y;
        }
        __syncthreads();

        // ---- scores: S[128][64] = Q @ K^T (split, 3 passes) ----
        float acc_s[2][4][4] = {};
        #pragma unroll
        for (int s = 0; s < 2; s++) {
            int kb = s * 16;
            uint32_t ah[2][4], al[2][4], bh[4][2], bl[4][2];
            #pragma unroll
            for (int mt = 0; mt < 2; mt++) {
                uint32_t addr = smem_u32(&sQh[(wm * 32 + mt * 16 + frow) * 40 + kb + fcolh]);
                ldsm_x4(ah[mt][0], ah[mt][1], ah[mt][2], ah[mt][3], addr);
                addr = smem_u32(&sQl[(wm * 32 + mt * 16 + frow) * 40 + kb + fcolh]);
                ldsm_x4(al[mt][0], al[mt][1], al[mt][2], al[mt][3], addr);
            }
            #pragma unroll
            for (int np = 0; np < 2; np++) {
                uint32_t r0, r1, r2, r3;
                uint32_t addr = smem_u32(&sKh[(wn * 32 + np * 16 + frow) * 40 + kb + fcolh]);
                ldsm_x4(r0, r1, r2, r3, addr);
                bh[np * 2][0] = r0; bh[np * 2 + 1][0] = r1;
                bh[np * 2][1] = r2; bh[np * 2 + 1][1] = r3;
                addr = smem_u32(&sKl[(wn * 32 + np * 16 + frow) * 40 + kb + fcolh]);
                ldsm_x4(r0, r1, r2, r3, addr);
                bl[np * 2][0] = r0; bl[np * 2 + 1][0] = r1;
                bl[np * 2][1] = r2; bl[np * 2 + 1][1] = r3;
            }
            #pragma unroll
            for (int mt = 0; mt < 2; mt++)
                #pragma unroll
                for (int nt = 0; nt < 4; nt++) {
                    mma_bf16(acc_s[mt][nt], ah[mt], bh[nt]);
                    mma_bf16(acc_s[mt][nt], ah[mt], bl[nt]);
                    mma_bf16(acc_s[mt][nt], al[mt], bh[nt]);
                }
        }

        // ---- e = scale*exp(s/sqrt(hd)) + 1 + bias; rowsum partials; split ----
        #pragma unroll
        for (int mt = 0; mt < 2; mt++) {
            #pragma unroll
            for (int half = 0; half < 2; half++) {
                int row = wm * 32 + mt * 16 + half * 8 + gid;
                #pragma unroll
                for (int nt = 0; nt < 4; nt++) {
                    float e0 = fmaf(scale, __expf(acc_s[mt][nt][half * 2 + 0] * inv_sqrt_hd), opb);
                    float e1 = fmaf(scale, __expf(acc_s[mt][nt][half * 2 + 1] * inv_sqrt_hd), opb);
                    rs[mt][half] += e0 + e1;
                    int col = wn * 32 + nt * 8 + tg * 2;
                    __nv_bfloat162 hh, ll;
                    split_bf16x2(e0, e1, hh, ll);
                    *(__nv_bfloat162*)&sEh[row * 72 + col] = hh;
                    *(__nv_bfloat162*)&sEl[row * 72 + col] = ll;
                }
            }
        }
        __syncthreads();

        // ---- EV += E[128][64] @ V[64][32] (split, 3 passes) ----
        #pragma unroll
        for (int kb = 0; kb < 64; kb += 16) {
            uint32_t eh[4], el[4], vh[4][2], vl[4][2];
            uint32_t addr = smem_u32(&sEh[(warp * 16 + frow) * 72 + kb + fcolh]);
            ldsm_x4(eh[0], eh[1], eh[2], eh[3], addr);
            addr = smem_u32(&sEl[(warp * 16 + frow) * 72 + kb + fcolh]);
            ldsm_x4(el[0], el[1], el[2], el[3], addr);
            #pragma unroll
            for (int np = 0; np < 2; np++) {
                uint32_t r0, r1, r2, r3;
                addr = smem_u32(&sVh[(np * 16 + frow) * 72 + kb + fcolh]);
                ldsm_x4(r0, r1, r2, r3, addr);
                vh[np * 2][0] = r0; vh[np * 2 + 1][0] = r1;
                vh[np * 2][1] = r2; vh[np * 2 + 1][1] = r3;
                addr = smem_u32(&sVl[(np * 16 + frow) * 72 + kb + fcolh]);
                ldsm_x4(r0, r1, r2, r3, addr);
                vl[np * 2][0] = r0; vl[np * 2 + 1][0] = r1;
                vl[np * 2][1] = r2; vl[np * 2 + 1][1] = r3;
            }
            #pragma unroll
            for (int nt = 0; nt < 4; nt++) {
                mma_bf16(acc_ev[nt], eh, vh[nt]);
                mma_bf16(acc_ev[nt], eh, vl[nt]);
                mma_bf16(acc_ev[nt], el, vh[nt]);
            }
        }
    }

    // ---- rowsum: quad-lane reduce + cross-warp smem atomics ----
    #pragma unroll
    for (int mt = 0; mt < 2; mt++)
        #pragma unroll
        for (int half = 0; half < 2; half++) {
            float v = rs[mt][half];
            v += __shfl_xor_sync(0xffffffffu, v, 1);
            v += __shfl_xor_sync(0xffffffffu, v, 2);
            if (tg == 0)
                atomicAdd(&rowsum[wm * 32 + mt * 16 + half * 8 + gid], v);
        }
    __syncthreads();

    // ---- epilogue: out = EV/denom (split bf16), unc += L/denom ----
    #pragma unroll
    for (int half = 0; half < 2; half++) {
        int row = warp * 16 + half * 8 + gid;
        float invd = 1.0f / rowsum[row];
        size_t obase = (size_t)b * SEQ * DMODEL + (size_t)(q0 + row) * DMODEL + h * HD;
        #pragma unroll
        for (int nt = 0; nt < 4; nt++) {
            int col = nt * 8 + tg * 2;
            float v0 = acc_ev[nt][half * 2 + 0] * invd;
            float v1 = acc_ev[nt][half * 2 + 1] * invd;
            __nv_bfloat162 hh, ll;
            split_bf16x2(v0, v1, hh, ll);
            *(__nv_bfloat162*)&outH[obase + col] = hh;
            *(__nv_bfloat162*)&outL[obase + col] = ll;
        }
        if (tg == 0)
            unc[(size_t)bh * SEQ + q0 + row] += (float)SEQ * invd;
    }
}

// ---------------- finalize --------------------------------------------------
__global__ void finalize_kernel(float* __restrict__ out)
{
    int i = blockIdx.x * blockDim.x + threadIdx.x;
    if (i < BATCH * NHEADS * SEQ) {
        float a = g_unc[i] * 0.25f;
        out[MTOT * DMODEL + i] = a;
        out[MTOT * DMODEL + BATCH * NHEADS * SEQ + i] = (a > 0.3f) ? 1.0f : 0.0f;
    }
}

// ---------------- launch ----------------------------------------------------
extern "C" void kernel_launch(void* const* d_in, const int* in_sizes, int n_in,
                              void* d_out, int out_size)
{
    const float* x      = (const float*)d_in[0];
    const float* Win    = (const float*)d_in[1];
    const float* bin_   = (const float*)d_in[2];
    const float* Wq     = (const float*)d_in[3];
    const float* bq     = (const float*)d_in[4];
    const float* Wk     = (const float*)d_in[5];
    const float* bk     = (const float*)d_in[6];
    const float* Wv     = (const float*)d_in[7];
    const float* bv     = (const float*)d_in[8];
    const float* Wo     = (const float*)d_in[9];
    const float* bo     = (const float*)d_in[10];
    const float* evs    = (const float*)d_in[11];
    const float* evb    = (const float*)d_in[12];
    const float* W1     = (const float*)d_in[13];
    const float* b1     = (const float*)d_in[14];
    const float* W2     = (const float*)d_in[15];
    const float* b2     = (const float*)d_in[16];
    const float* n1g    = (const float*)d_in[17];
    const float* n1b    = (const float*)d_in[18];
    const float* n2g    = (const float*)d_in[19];
    const float* n2b    = (const float*)d_in[20];
    const float* fng    = (const float*)d_in[21];
    const float* fnb    = (const float*)d_in[22];
    const float* Wout   = (const float*)d_in[23];
    const float* bout   = (const float*)d_in[24];
    float* out = (float*)d_out;

    float *ph, *punc, *pbqkv;
    cudaGetSymbolAddress((void**)&ph,    g_h);
    cudaGetSymbolAddress((void**)&punc,  g_unc);
    cudaGetSymbolAddress((void**)&pbqkv, g_bqkv);

    __nv_bfloat16 *xH, *xL, *lnH, *lnL, *qkvH, *qkvL, *attnH, *attnL, *ffH, *ffL;
    cudaGetSymbolAddress((void**)&xH,    g_xH);
    cudaGetSymbolAddress((void**)&xL,    g_xL);
    cudaGetSymbolAddress((void**)&lnH,   g_lnH);
    cudaGetSymbolAddress((void**)&lnL,   g_lnL);
    cudaGetSymbolAddress((void**)&qkvH,  g_qkvH);
    cudaGetSymbolAddress((void**)&qkvL,  g_qkvL);
    cudaGetSymbolAddress((void**)&attnH, g_attnH);
    cudaGetSymbolAddress((void**)&attnL, g_attnL);
    cudaGetSymbolAddress((void**)&ffH,   g_ffH);
    cudaGetSymbolAddress((void**)&ffL,   g_ffL);

    __nv_bfloat16 *WinH, *WinL, *WoutH, *WoutL, *WqkvH, *WqkvL,
                  *WoH, *WoL, *W1H, *W1L, *W2H, *W2L;
    cudaGetSymbolAddress((void**)&WinH,  g_WinH);
    cudaGetSymbolAddress((void**)&WinL,  g_WinL);
    cudaGetSymbolAddress((void**)&WoutH, g_WoutH);
    cudaGetSymbolAddress((void**)&WoutL, g_WoutL);
    cudaGetSymbolAddress((void**)&WqkvH, g_WqkvH);
    cudaGetSymbolAddress((void**)&WqkvL, g_WqkvL);
    cudaGetSymbolAddress((void**)&WoH,   g_WoH);
    cudaGetSymbolAddress((void**)&WoL,   g_WoL);
    cudaGetSymbolAddress((void**)&W1H,   g_W1H);
    cudaGetSymbolAddress((void**)&W1L,   g_W1L);
    cudaGetSymbolAddress((void**)&W2H,   g_W2H);
    cudaGetSymbolAddress((void**)&W2L,   g_W2L);

    cudaFuncSetAttribute(attn_mma, cudaFuncAttributeMaxDynamicSharedMemorySize, ATTN_SMEM);
    cudaFuncSetAttribute(gemm2<0,0>, cudaFuncAttributeMaxDynamicSharedMemorySize, GEMM_SMEM);
    cudaFuncSetAttribute(gemm2<0,1>, cudaFuncAttributeMaxDynamicSharedMemorySize, GEMM_SMEM);
    cudaFuncSetAttribute(gemm2<1,0>, cudaFuncAttributeMaxDynamicSharedMemorySize, GEMM_SMEM);
    cudaFuncSetAttribute(gemm2<2,1>, cudaFuncAttributeMaxDynamicSharedMemorySize, GEMM_SMEM);

    // ---- prep: split weights (transposed) + input x + biases ----
    PrepArgs pa;
    int si = 0;
    pa.s[si++] = { Win,  WinH,  WinL,  DMODEL, DMODEL };
    pa.s[si++] = { Wout, WoutH, WoutL, DMODEL, DMODEL };
    for (int i = 0; i < NLAYERS; i++) {
        size_t qb = (size_t)i * QKVS * DMODEL;
        pa.s[si++] = { Wq + (size_t)i * DMODEL * DMODEL, WqkvH + qb,                       WqkvL + qb,                       DMODEL, DMODEL };
        pa.s[si++] = { Wk + (size_t)i * DMODEL * DMODEL, WqkvH + qb + DMODEL * DMODEL,     WqkvL + qb + DMODEL * DMODEL,     DMODEL, DMODEL };
        pa.s[si++] = { Wv + (size_t)i * DMODEL * DMODEL, WqkvH + qb + 2 * DMODEL * DMODEL, WqkvL + qb + 2 * DMODEL * DMODEL, DMODEL, DMODEL };
        pa.s[si++] = { Wo + (size_t)i * DMODEL * DMODEL, WoH + (size_t)i * DMODEL * DMODEL, WoL + (size_t)i * DMODEL * DMODEL, DMODEL, DMODEL };
        pa.s[si++] = { W1 + (size_t)i * DMODEL * DFF, W1H + (size_t)i * DFF * DMODEL, W1L + (size_t)i * DFF * DMODEL, DMODEL, DFF };
        pa.s[si++] = { W2 + (size_t)i * DFF * DMODEL, W2H + (size_t)i * DMODEL * DFF, W2L + (size_t)i * DMODEL * DFF, DFF, DMODEL };
    }

    prep_kernel<<<dim3((DFF * DMODEL + 255) / 256, 26), 256>>>(pa);
    splitx_kernel<<<(MTOT * DMODEL + 255) / 256, 256>>>(x);
    misc_kernel<<<(NLAYERS * QKVS + BATCH * NHEADS * SEQ + 255) / 256, 256>>>(bq, bk, bv);

    const dim3 gD(DMODEL / 64, MTOT / 128);   // (4, 32)  = 128 blocks
    const dim3 gQ(QKVS   / 64, MTOT / 128);   // (12, 32) = 384
    const dim3 gF(DFF    / 64, MTOT / 128);   // (16, 32) = 512
    const dim3 gA(SEQ / 128, BATCH * NHEADS);

    // h = x @ Win + bin   (fp32 out -> residual stream)
    gemm2<0,0><<<gD, 256, GEMM_SMEM>>>(xH, xL, WinH, WinL, bin_, nullptr,
                                       ph, nullptr, nullptr, DMODEL, DMODEL);

    for (int i = 0; i < NLAYERS; i++) {
        ln_kernel<<<MTOT, 256>>>(ph, n1g + i * DMODEL, n1b + i * DMODEL, lnH, lnL);
        // fused QKV (split bf16 out)
        gemm2<0,1><<<gQ, 256, GEMM_SMEM>>>(lnH, lnL,
                                           WqkvH + (size_t)i * QKVS * DMODEL,
                                           WqkvL + (size_t)i * QKVS * DMODEL,
                                           pbqkv + i * QKVS, nullptr,
                                           nullptr, qkvH, qkvL, DMODEL, QKVS);
        attn_mma<<<gA, 256, ATTN_SMEM>>>(qkvH, qkvL, attnH, attnL, punc, evs, evb, i);
        // h = h + attn @ Wo + bo
        gemm2<1,0><<<gD, 256, GEMM_SMEM>>>(attnH, attnL,
                                           WoH + (size_t)i * DMODEL * DMODEL,
                                           WoL + (size_t)i * DMODEL * DMODEL,
                                           bo + i * DMODEL, ph,
                                           ph, nullptr, nullptr, DMODEL, DMODEL);
        ln_kernel<<<MTOT, 256>>>(ph, n2g + i * DMODEL, n2b + i * DMODEL, lnH, lnL);
        // ff = gelu(ln2 @ W1 + b1)  (split bf16 out)
        gemm2<2,1><<<gF, 256, GEMM_SMEM>>>(lnH, lnL,
                                           W1H + (size_t)i * DFF * DMODEL,
                                           W1L + (size_t)i * DFF * DMODEL,
                                           b1 + i * DFF, nullptr,
                                           nullptr, ffH, ffL, DMODEL, DFF);
        // h = h + ff @ W2 + b2
        gemm2<1,0><<<gD, 256, GEMM_SMEM>>>(ffH, ffL,
                                           W2H + (size_t)i * DMODEL * DFF,
                                           W2L + (size_t)i * DMODEL * DFF,
                                           b2 + i * DMODEL, ph,
                                           ph, nullptr, nullptr, DFF, DMODEL);
    }

    ln_kernel<<<MTOT, 256>>>(ph, fng, fnb, lnH, lnL);
    gemm2<0,0><<<gD, 256, GEMM_SMEM>>>(lnH, lnL, WoutH, WoutL, bout, nullptr,
                                       out, nullptr, nullptr, DMODEL, DMODEL);

    if (out_size >= MTOT * DMODEL + 2 * BATCH * NHEADS * SEQ)
        finalize_kernel<<<(BATCH * NHEADS * SEQ + 255) / 256, 256>>>(out);
}